// round 7
// baseline (speedup 1.0000x reference)
#include <cuda_runtime.h>
#include <cuda_fp16.h>
#include <math.h>
#include <stdint.h>

#define NB     256
#define CDIM   1024
#define GROUPS 8
#define CG     128
#define DH     64
#define SP     64
#define NG     (NB*GROUPS)

// ---------------- scratch ----------------
__device__ float g_xn[NB*CDIM*SP];
__device__ float g_vgrid[NG*4*2];
__device__ float g_v [NG*DH*4];
__device__ float g_sim [NG*SP*4];
__device__ float g_ao[NB*SP*512];        // attention out TRANSPOSED: [n][s][c]

__device__ __forceinline__ uint32_t pack2(float x, float y) {
    __half2 h = __floats2half2_rn(x, y);
    return *(uint32_t*)&h;
}
__device__ __forceinline__ uint32_t smem_u32(const void* p) {
    uint32_t a;
    asm("{ .reg .u64 t; cvta.to.shared.u64 t, %1; cvt.u32.u64 %0, t; }" : "=r"(a) : "l"(p));
    return a;
}

// ---------------- K1: LayerNorm + patchify ----------------
__global__ __launch_bounds__(256) void k1_ln(const float* __restrict__ x,
                                             const float* __restrict__ lng,
                                             const float* __restrict__ lnb) {
    int bid = blockIdx.x;
    int bi = bid >> 4, y = bid & 15;
    int t = threadIdx.x;
    int xcol = t & 15, ci = t >> 4;
    const float* px = x + (size_t)bi*CDIM*256 + y*16 + xcol;
    float s1 = 0.f, s2 = 0.f;
    for (int m = 0; m < 64; m++) {
        float v = px[(ci + 16*m)*256];
        s1 += v; s2 += v*v;
    }
    __shared__ float sm1[16][17], sm2[16][17];
    sm1[ci][xcol] = s1; sm2[ci][xcol] = s2;
    __syncthreads();
    for (int st = 8; st > 0; st >>= 1) {
        if (ci < st) { sm1[ci][xcol] += sm1[ci+st][xcol]; sm2[ci][xcol] += sm2[ci+st][xcol]; }
        __syncthreads();
    }
    float mu  = sm1[0][xcol] * (1.f/1024.f);
    float var = sm2[0][xcol] * (1.f/1024.f) - mu*mu;
    float rstd = rsqrtf(var + 1e-6f);
    int n = ((y>>3)*2 + (xcol>>3))*64 + bi;
    int s = (y&7)*8 + (xcol&7);
    float* po = g_xn + (size_t)n*CDIM*SP + s;
    for (int m = 0; m < 64; m++) {
        int c = ci + 16*m;
        float v = px[c*256];
        po[c*SP] = (v - mu)*rstd*lng[c] + lnb[c];
    }
}

// ---------------- K234: q proj + offsets + grid-sample + k/v proj + sim ----------------
#define K234_SMEM 72192
__global__ __launch_bounds__(256,1) void k234(const float* __restrict__ wq,
                                              const float* __restrict__ ow1,
                                              const float* __restrict__ ob1,
                                              const float* __restrict__ ow2,
                                              const float* __restrict__ wk,
                                              const float* __restrict__ wv) {
    extern __shared__ float sm[];
    float* xs  = sm;                 // [128][65]
    float* qs  = xs + 128*65;        // [64][65]
    float* ws  = qs + 64*65;         // [64][66]
    float* kvs = ws + 64*66;         // [128][5]
    float* ksm = kvs + 128*5;        // [64][5]
    float* go  = ksm + 64*5;         // [4][64]
    float* vgr = go + 256;           // [8]
    int*   ip  = (int*)(vgr + 8);    // ix0[4], iy0[4]
    float* wxy = (float*)(ip + 8);   // wx1[4], wy1[4]

    int ng = blockIdx.x; int n = ng >> 3, g = ng & 7;
    int t = threadIdx.x;

    const float* xb = g_xn + (size_t)(n*CDIM + g*CG)*SP;
    #pragma unroll
    for (int i = 0; i < 32; i++) {
        int idx = t + 256*i;
        xs[(idx>>6)*65 + (idx&63)] = xb[idx];
    }
    __syncthreads();

    int ts = t & 15, td = t >> 4;
    {
        float acc[4][4];
        #pragma unroll
        for (int i=0;i<4;i++)
            #pragma unroll
            for (int j=0;j<4;j++) acc[i][j]=0.f;
        const float* wb = wq + (size_t)(g*DH)*CG;
        #pragma unroll
        for (int kc = 0; kc < 128; kc += 64) {
            #pragma unroll
            for (int m = 0; m < 16; m++) {
                int idx = t + 256*m;
                ws[(idx>>6)*66 + (idx&63)] = wb[(idx>>6)*CG + kc + (idx&63)];
            }
            __syncthreads();
            for (int k = 0; k < 64; k++) {
                float wv4[4], xv[4];
                #pragma unroll
                for (int i=0;i<4;i++) { wv4[i]=ws[(td*4+i)*66 + k]; xv[i]=xs[(kc+k)*65 + ts*4+i]; }
                #pragma unroll
                for (int i=0;i<4;i++)
                    #pragma unroll
                    for (int j=0;j<4;j++) acc[i][j] = fmaf(wv4[i], xv[j], acc[i][j]);
            }
            __syncthreads();
        }
        #pragma unroll
        for (int i=0;i<4;i++)
            #pragma unroll
            for (int j=0;j<4;j++) qs[(td*4+i)*65 + ts*4+j] = acc[i][j];
    }
    __syncthreads();

    {
        int o = t >> 2, oi = t & 3, oy = oi >> 1, ox = oi & 1;
        float acc = ob1[o];
        #pragma unroll
        for (int ky=0;ky<6;ky++){
            int iy = 4*oy - 1 + ky;
            if (iy < 0 || iy > 7) continue;
            #pragma unroll
            for (int kx=0;kx<6;kx++){
                int ix = 4*ox - 1 + kx;
                if (ix < 0 || ix > 7) continue;
                acc = fmaf(qs[o*65 + iy*8+ix], ow1[o*36 + ky*6 + kx], acc);
            }
        }
        go[oi*64 + o] = 0.5f*acc*(1.f + erff(acc*0.70710678118654752f));
    }
    __syncthreads();
    if (t < 8) {
        int j = t >> 1, oo = t & 1;
        float s = 0.f;
        for (int c=0;c<64;c++) s = fmaf(go[j*64+c], ow2[oo*64+c], s);
        float off = tanhf(s)*4.0f;
        float base = (oo==0) ? (float)(j&1) : (float)(j>>1);
        float vg = 2.f*(base + off) - 1.f;
        vgr[j*2+oo] = vg;
        g_vgrid[(ng*4+j)*2+oo] = vg;
    }
    __syncthreads();
    if (t < 4) {
        float fx = ((vgr[t*2+0]+1.f)*8.f - 1.f)*0.5f;
        float fy = ((vgr[t*2+1]+1.f)*8.f - 1.f)*0.5f;
        float x0 = floorf(fx), y0 = floorf(fy);
        ip[t] = (int)x0; ip[4+t] = (int)y0;
        wxy[t] = fx - x0; wxy[4+t] = fy - y0;
    }
    __syncthreads();

    if (t < 128) {
        const float* img = xs + t*65;
        #pragma unroll
        for (int j=0;j<4;j++){
            int x0=ip[j], y0=ip[4+j];
            float wx1=wxy[j], wy1=wxy[4+j], wx0=1.f-wx1, wy0=1.f-wy1;
            bool xa = (x0>=0 && x0<8), xc = (x0+1>=0 && x0+1<8);
            bool ya = (y0>=0 && y0<8), yc = (y0+1>=0 && y0+1<8);
            float v00 = (xa&&ya)? img[y0*8+x0]       : 0.f;
            float v01 = (xc&&ya)? img[y0*8+x0+1]     : 0.f;
            float v10 = (xa&&yc)? img[(y0+1)*8+x0]   : 0.f;
            float v11 = (xc&&yc)? img[(y0+1)*8+x0+1] : 0.f;
            kvs[t*5+j] = v00*wx0*wy0 + v01*wx1*wy0 + v10*wx0*wy1 + v11*wx1*wy1;
        }
    }
    __syncthreads();

    int o4 = t >> 2, j4 = t & 3;
    {
        const float* wkb = wk + (size_t)g*DH*CG;
        const float* wvb = wv + (size_t)g*DH*CG;
        float ak = 0.f, av = 0.f;
        #pragma unroll
        for (int half = 0; half < 4; half++) {
            const float* wsrc = (half < 2) ? wkb : wvb;
            int ic = (half & 1) * 64;
            #pragma unroll
            for (int m = 0; m < 4; m++) {
                int fl4 = t + 256*m;
                int oL = fl4 >> 4, ii = (fl4 & 15) * 4;
                float4 v4 = *(const float4*)(wsrc + (size_t)oL*CG + ic + ii);
                ws[oL*66+ii] = v4.x; ws[oL*66+ii+1] = v4.y; ws[oL*66+ii+2] = v4.z; ws[oL*66+ii+3] = v4.w;
            }
            __syncthreads();
            float acc = 0.f;
            #pragma unroll 8
            for (int i = 0; i < 64; i++) acc = fmaf(kvs[(ic+i)*5 + j4], ws[o4*66+i], acc);
            if (half < 2) ak += acc; else av += acc;
            __syncthreads();
        }
        ksm[o4*5+j4] = ak;
        g_v[(size_t)(ng*DH+o4)*4+j4] = av;
    }
    __syncthreads();

    {
        int s4 = t >> 2;
        float a = 0.f;
        for (int d = 0; d < 64; d++) a = fmaf(qs[d*65+s4], ksm[d*5+j4], a);
        g_sim[(size_t)ng*256 + s4*4 + j4] = a*0.125f;
    }
}

// ---------------- K56: CPB MLP (h1 in smem + ldmatrix) fused with softmax+AV ----------------
// CTA = 256 rows = one ng. h1h: swizzled half [256 r][256 k] (128 KB).
#define K56_SMEM (131072 + 33792 + 11264)
__global__ __launch_bounds__(256,1) void k56(const float* __restrict__ w1,
                                             const float* __restrict__ b1,
                                             const float* __restrict__ w2,
                                             const float* __restrict__ b2,
                                             const float* __restrict__ w3,
                                             const float* __restrict__ b3) {
    extern __shared__ char smraw[];
    __half* w2h = (__half*)(smraw + 131072);          // [64 n][264 k halves]
    float* fl   = (float*)(smraw + 131072 + 33792);
    float* uu   = fl;          // [256]
    float* vv   = fl + 256;
    float* b2s  = fl + 512;
    float* w3s  = fl + 768;
    float* w1as = fl + 1024;
    float* w1bs = fl + 1280;
    float* b1s  = fl + 1536;
    float* biass= fl + 1792;   // [256]
    float* att  = fl + 2048;   // [64][5]
    float* vsm  = fl + 2368;   // [64][5]
    uint32_t sbase = smem_u32(smraw);

    int ng = blockIdx.x;
    int t = threadIdx.x;
    int lane = t & 31, w = t >> 5;
    int lq = lane >> 2, la3 = lane & 3;

    {
        int s = t >> 2, j = t & 3;
        float qx = (float)(s & 7)*(2.f/7.f) - 1.f;
        float qy = (float)(s >> 3)*(2.f/7.f) - 1.f;
        float vx = g_vgrid[(ng*4+j)*2+0];
        float vy = g_vgrid[(ng*4+j)*2+1];
        float px = qx - vx, py = qy - vy;
        uu[t] = copysignf(log1pf(fabsf(px)), px);
        vv[t] = copysignf(log1pf(fabsf(py)), py);
    }
    b2s[t] = b2[t]; w3s[t] = w3[t];
    w1as[t] = w1[t]; w1bs[t] = w1[256+t]; b1s[t] = b1[t];
    __syncthreads();

    // ---- h1 fill: 8192 16B-quads; warp covers one row per iter (conflict-free) ----
    #pragma unroll
    for (int i = 0; i < 32; i++) {
        int idx = t + 256*i;
        int r = idx >> 5, kq = idx & 31;        // 32 quads of 16B per 512B row
        float u = uu[r], v = vv[r];
        int k = kq*8;
        float4 wa0 = *(float4*)&w1as[k],  wa1 = *(float4*)&w1as[k+4];
        float4 wb0 = *(float4*)&w1bs[k],  wb1 = *(float4*)&w1bs[k+4];
        float4 bb0 = *(float4*)&b1s[k],   bb1 = *(float4*)&b1s[k+4];
        uint4 pk;
        pk.x = pack2(fmaxf(fmaf(u,wa0.x,fmaf(v,wb0.x,bb0.x)),0.f),
                     fmaxf(fmaf(u,wa0.y,fmaf(v,wb0.y,bb0.y)),0.f));
        pk.y = pack2(fmaxf(fmaf(u,wa0.z,fmaf(v,wb0.z,bb0.z)),0.f),
                     fmaxf(fmaf(u,wa0.w,fmaf(v,wb0.w,bb0.w)),0.f));
        pk.z = pack2(fmaxf(fmaf(u,wa1.x,fmaf(v,wb1.x,bb1.x)),0.f),
                     fmaxf(fmaf(u,wa1.y,fmaf(v,wb1.y,bb1.y)),0.f));
        pk.w = pack2(fmaxf(fmaf(u,wa1.z,fmaf(v,wb1.z,bb1.z)),0.f),
                     fmaxf(fmaf(u,wa1.w,fmaf(v,wb1.w,bb1.w)),0.f));
        int phys = r*512 + ((kq*16) ^ ((r&31)<<4));
        *(uint4*)(smraw + phys) = pk;
    }

    // per-warp ldmatrix row constants (warp owns rows 32w..32w+31; mt in {0,1})
    int rin = lane & 15;
    int koff = (lane >> 4) * 16;
    int rowoff[2], swz[2];
    #pragma unroll
    for (int mt = 0; mt < 2; mt++) {
        int row = 32*w + mt*16 + rin;
        rowoff[mt] = row*512;
        swz[mt] = (row & 31) << 4;
    }

    float accR[4] = {0.f, 0.f, 0.f, 0.f};

    for (int ct = 0; ct < 4; ct++) {
        __syncthreads();
        #pragma unroll
        for (int i = 0; i < 32; i++) {
            int idx = t + 256*i;
            int nn = idx & 63, kp = idx >> 6;
            *(uint32_t*)&w2h[nn*264 + 2*kp] =
                pack2(w2[(2*kp)*256 + ct*64 + nn], w2[(2*kp+1)*256 + ct*64 + nn]);
        }
        __syncthreads();

        float C[2][8][4];
        #pragma unroll
        for (int mt=0;mt<2;mt++)
            #pragma unroll
            for (int nt=0;nt<8;nt++)
                #pragma unroll
                for (int i=0;i<4;i++) C[mt][nt][i]=0.f;

        #pragma unroll 4
        for (int ks = 0; ks < 16; ks++) {
            uint32_t a[2][4];
            #pragma unroll
            for (int mt = 0; mt < 2; mt++) {
                uint32_t addr = sbase + rowoff[mt] + ((ks*32 + koff) ^ swz[mt]);
                asm volatile("ldmatrix.sync.aligned.m8n8.x4.shared.b16 {%0,%1,%2,%3}, [%4];"
                    : "=r"(a[mt][0]), "=r"(a[mt][1]), "=r"(a[mt][2]), "=r"(a[mt][3])
                    : "r"(addr));
            }
            int k0 = ks*16 + 2*la3;
            #pragma unroll
            for (int nt = 0; nt < 8; nt++) {
                int nb = (nt*8 + lq)*264;
                uint32_t b0 = *(uint32_t*)&w2h[nb + k0];
                uint32_t b1v= *(uint32_t*)&w2h[nb + k0 + 8];
                #pragma unroll
                for (int mt = 0; mt < 2; mt++) {
                    asm volatile(
                        "mma.sync.aligned.m16n8k16.row.col.f32.f16.f16.f32 "
                        "{%0,%1,%2,%3}, {%4,%5,%6,%7}, {%8,%9}, {%0,%1,%2,%3};"
                        : "+f"(C[mt][nt][0]), "+f"(C[mt][nt][1]),
                          "+f"(C[mt][nt][2]), "+f"(C[mt][nt][3])
                        : "r"(a[mt][0]), "r"(a[mt][1]), "r"(a[mt][2]), "r"(a[mt][3]),
                          "r"(b0), "r"(b1v));
                }
            }
        }
        #pragma unroll
        for (int mt = 0; mt < 2; mt++)
            #pragma unroll
            for (int nt = 0; nt < 8; nt++) {
                int col = ct*64 + nt*8 + la3*2;
                float bb0 = b2s[col],   w30 = w3s[col];
                float bb1 = b2s[col+1], w31 = w3s[col+1];
                accR[mt*2+0] = fmaf(fmaxf(C[mt][nt][0]+bb0, 0.f), w30,
                               fmaf(fmaxf(C[mt][nt][1]+bb1, 0.f), w31, accR[mt*2+0]));
                accR[mt*2+1] = fmaf(fmaxf(C[mt][nt][2]+bb0, 0.f), w30,
                               fmaf(fmaxf(C[mt][nt][3]+bb1, 0.f), w31, accR[mt*2+1]));
            }
    }
    #pragma unroll
    for (int i = 0; i < 4; i++) {
        accR[i] += __shfl_xor_sync(0xffffffffu, accR[i], 1);
        accR[i] += __shfl_xor_sync(0xffffffffu, accR[i], 2);
    }
    if (la3 == 0) {
        float bz = b3[0];
        int base = 32*w;
        #pragma unroll
        for (int mt = 0; mt < 2; mt++) {
            biass[base + mt*16 + lq]     = accR[2*mt]   + bz;
            biass[base + mt*16 + 8 + lq] = accR[2*mt+1] + bz;
        }
    }
    __syncthreads();

    // ---- fused softmax(4) + attn @ v ----
    {
        int s = t >> 2, j = t & 3;
        float e = g_sim[(size_t)ng*256 + t] + biass[t];
        float m = e;
        m = fmaxf(m, __shfl_xor_sync(0xffffffffu, m, 1));
        m = fmaxf(m, __shfl_xor_sync(0xffffffffu, m, 2));
        float ex = __expf(e - m);
        float ssum = ex;
        ssum += __shfl_xor_sync(0xffffffffu, ssum, 1);
        ssum += __shfl_xor_sync(0xffffffffu, ssum, 2);
        att[s*5 + j] = ex / ssum;
        vsm[s*5 + j] = g_v[(size_t)ng*256 + t];   // s here indexes d
    }
    __syncthreads();
    {
        int n = ng >> 3, g = ng & 7;
        int tsg = t >> 4, tdg = t & 15;
        float* ab = g_ao + (size_t)n*SP*512 + g*64;
        #pragma unroll
        for (int ss=0; ss<4; ss++) {
            int s = tsg*4 + ss;
            #pragma unroll
            for (int dd=0; dd<4; dd++) {
                int d = tdg*4 + dd;
                float a = att[s*5+0]*vsm[d*5+0] + att[s*5+1]*vsm[d*5+1]
                        + att[s*5+2]*vsm[d*5+2] + att[s*5+3]*vsm[d*5+3];
                ab[(size_t)s*512 + d] = a;
            }
        }
    }
}

// ---------------- K7: final projection via fp16 mma + stitch ----------------
__global__ __launch_bounds__(256,2) void k7_out(const float* __restrict__ ow,
                                                const float* __restrict__ ob,
                                                float* __restrict__ out) {
    __shared__ __half a_h[128*40];
    __shared__ __half w_h[128*40];
    int bid = blockIdx.x;
    int m0 = (bid >> 3) * 128, n0 = (bid & 7) * 128;
    int t = threadIdx.x;
    int lane = t & 31, w = t >> 5;
    int lq = lane >> 2, la3 = lane & 3;
    int wm = (w >> 1) * 32, wn = (w & 1) * 64;

    float C[2][8][4];
    #pragma unroll
    for (int mt=0;mt<2;mt++)
        #pragma unroll
        for (int nt=0;nt<8;nt++)
            #pragma unroll
            for (int i=0;i<4;i++) C[mt][nt][i]=0.f;

    for (int kc = 0; kc < 16; kc++) {
        __syncthreads();
        #pragma unroll
        for (int i = 0; i < 4; i++) {
            int idx = t + 256*i;
            int row = idx >> 3, k4 = (idx & 7) * 4;
            float4 va = *(const float4*)(g_ao + (size_t)(m0+row)*512 + kc*32 + k4);
            *(uint32_t*)&a_h[row*40 + k4]     = pack2(va.x, va.y);
            *(uint32_t*)&a_h[row*40 + k4 + 2] = pack2(va.z, va.w);
            float4 vw = *(const float4*)(ow + (size_t)(n0+row)*512 + kc*32 + k4);
            *(uint32_t*)&w_h[row*40 + k4]     = pack2(vw.x, vw.y);
            *(uint32_t*)&w_h[row*40 + k4 + 2] = pack2(vw.z, vw.w);
        }
        __syncthreads();
        #pragma unroll
        for (int ks = 0; ks < 2; ks++) {
            int k0 = ks*16 + 2*la3;
            uint32_t a[2][4];
            #pragma unroll
            for (int mt = 0; mt < 2; mt++) {
                int ar = wm + mt*16 + lq;
                a[mt][0] = *(uint32_t*)&a_h[ar*40 + k0];
                a[mt][1] = *(uint32_t*)&a_h[(ar+8)*40 + k0];
                a[mt][2] = *(uint32_t*)&a_h[ar*40 + k0 + 8];
                a[mt][3] = *(uint32_t*)&a_h[(ar+8)*40 + k0 + 8];
            }
            #pragma unroll
            for (int nt = 0; nt < 8; nt++) {
                int br = wn + nt*8 + lq;
                uint32_t b0 = *(uint32_t*)&w_h[br*40 + k0];
                uint32_t b1v= *(uint32_t*)&w_h[br*40 + k0 + 8];
                #pragma unroll
                for (int mt = 0; mt < 2; mt++) {
                    asm volatile(
                        "mma.sync.aligned.m16n8k16.row.col.f32.f16.f16.f32 "
                        "{%0,%1,%2,%3}, {%4,%5,%6,%7}, {%8,%9}, {%0,%1,%2,%3};"
                        : "+f"(C[mt][nt][0]), "+f"(C[mt][nt][1]),
                          "+f"(C[mt][nt][2]), "+f"(C[mt][nt][3])
                        : "r"(a[mt][0]), "r"(a[mt][1]), "r"(a[mt][2]), "r"(a[mt][3]),
                          "r"(b0), "r"(b1v));
                }
            }
        }
    }

    int mbase[2][2];
    #pragma unroll
    for (int mt = 0; mt < 2; mt++) {
        #pragma unroll
        for (int h = 0; h < 2; h++) {
            int m = m0 + wm + mt*16 + h*8 + lq;
            int np = m >> 6, s = m & 63;
            int bi = np & 63, q = np >> 6;
            int Y = (q >> 1)*8 + (s >> 3);
            int X = (q & 1)*8 + (s & 7);
            mbase[mt][h] = bi*262144 + Y*16 + X;
        }
    }
    #pragma unroll
    for (int nt = 0; nt < 8; nt++) {
        int o = n0 + wn + nt*8 + la3*2;
        float ob0 = ob[o], ob1 = ob[o+1];
        #pragma unroll
        for (int mt = 0; mt < 2; mt++) {
            out[mbase[mt][0] + o*256]       = C[mt][nt][0] + ob0;
            out[mbase[mt][0] + (o+1)*256]   = C[mt][nt][1] + ob1;
            out[mbase[mt][1] + o*256]       = C[mt][nt][2] + ob0;
            out[mbase[mt][1] + (o+1)*256]   = C[mt][nt][3] + ob1;
        }
    }
}

// ---------------- launch ----------------
extern "C" void kernel_launch(void* const* d_in, const int* in_sizes, int n_in,
                              void* d_out, int out_size) {
    const float* x      = (const float*)d_in[0];
    const float* ln_g   = (const float*)d_in[1];
    const float* ln_b   = (const float*)d_in[2];
    const float* wq     = (const float*)d_in[3];
    const float* wk     = (const float*)d_in[4];
    const float* wv     = (const float*)d_in[5];
    const float* off_w1 = (const float*)d_in[6];
    const float* off_b1 = (const float*)d_in[7];
    const float* off_w2 = (const float*)d_in[8];
    const float* cpb_w1 = (const float*)d_in[9];
    const float* cpb_b1 = (const float*)d_in[10];
    const float* cpb_w2 = (const float*)d_in[11];
    const float* cpb_b2 = (const float*)d_in[12];
    const float* cpb_w3 = (const float*)d_in[13];
    const float* cpb_b3 = (const float*)d_in[14];
    const float* out_w  = (const float*)d_in[15];
    const float* out_b  = (const float*)d_in[16];
    float* out = (float*)d_out;

    static int attr_done = 0;
    if (!attr_done) {
        cudaFuncSetAttribute(k234, cudaFuncAttributeMaxDynamicSharedMemorySize, K234_SMEM);
        cudaFuncSetAttribute(k56, cudaFuncAttributeMaxDynamicSharedMemorySize, K56_SMEM);
        attr_done = 1;
    }

    k1_ln <<<1024, 256>>>(x, ln_g, ln_b);
    k234  <<<2048, 256, K234_SMEM>>>(wq, off_w1, off_b1, off_w2, wk, wv);
    k56   <<<2048, 256, K56_SMEM>>>(cpb_w1, cpb_b1, cpb_w2, cpb_b2, cpb_w3, cpb_b3);
    k7_out<<<1024, 256>>>(out_w, out_b, out);
}

// round 8
// speedup vs baseline: 1.0195x; 1.0195x over previous
#include <cuda_runtime.h>
#include <cuda_fp16.h>
#include <math.h>
#include <stdint.h>

#define NB     256
#define CDIM   1024
#define GROUPS 8
#define CG     128
#define DH     64
#define SP     64
#define NG     (NB*GROUPS)

// ---------------- scratch ----------------
__device__ float g_xn[NB*CDIM*SP];
__device__ float g_vgrid[NG*4*2];
__device__ float g_v [NG*DH*4];
__device__ float g_sim [NG*SP*4];
__device__ float g_bias[NG*SP*4];
__device__ float g_ao[NB*SP*512];        // attention out TRANSPOSED: [n][s][c]

__device__ __forceinline__ uint32_t pack2(float x, float y) {
    __half2 h = __floats2half2_rn(x, y);
    return *(uint32_t*)&h;
}

// ---------------- K1: LayerNorm + patchify ----------------
__global__ __launch_bounds__(256) void k1_ln(const float* __restrict__ x,
                                             const float* __restrict__ lng,
                                             const float* __restrict__ lnb) {
    int bid = blockIdx.x;
    int bi = bid >> 4, y = bid & 15;
    int t = threadIdx.x;
    int xcol = t & 15, ci = t >> 4;
    const float* px = x + (size_t)bi*CDIM*256 + y*16 + xcol;
    float s1 = 0.f, s2 = 0.f;
    for (int m = 0; m < 64; m++) {
        float v = px[(ci + 16*m)*256];
        s1 += v; s2 += v*v;
    }
    __shared__ float sm1[16][17], sm2[16][17];
    sm1[ci][xcol] = s1; sm2[ci][xcol] = s2;
    __syncthreads();
    for (int st = 8; st > 0; st >>= 1) {
        if (ci < st) { sm1[ci][xcol] += sm1[ci+st][xcol]; sm2[ci][xcol] += sm2[ci+st][xcol]; }
        __syncthreads();
    }
    float mu  = sm1[0][xcol] * (1.f/1024.f);
    float var = sm2[0][xcol] * (1.f/1024.f) - mu*mu;
    float rstd = rsqrtf(var + 1e-6f);
    int n = ((y>>3)*2 + (xcol>>3))*64 + bi;
    int s = (y&7)*8 + (xcol&7);
    float* po = g_xn + (size_t)n*CDIM*SP + s;
    for (int m = 0; m < 64; m++) {
        int c = ci + 16*m;
        float v = px[c*256];
        po[c*SP] = (v - mu)*rstd*lng[c] + lnb[c];
    }
}

// ---------------- K234: q proj + offsets + grid-sample + k/v proj + sim ----------------
#define K234_SMEM 72192
__global__ __launch_bounds__(256,1) void k234(const float* __restrict__ wq,
                                              const float* __restrict__ ow1,
                                              const float* __restrict__ ob1,
                                              const float* __restrict__ ow2,
                                              const float* __restrict__ wk,
                                              const float* __restrict__ wv) {
    extern __shared__ float sm[];
    float* xs  = sm;                 // [128][65]
    float* qs  = xs + 128*65;        // [64][65]
    float* ws  = qs + 64*65;         // [64][66]
    float* kvs = ws + 64*66;         // [128][5]
    float* ksm = kvs + 128*5;        // [64][5]
    float* go  = ksm + 64*5;         // [4][64]
    float* vgr = go + 256;           // [8]
    int*   ip  = (int*)(vgr + 8);    // ix0[4], iy0[4]
    float* wxy = (float*)(ip + 8);   // wx1[4], wy1[4]

    int ng = blockIdx.x; int n = ng >> 3, g = ng & 7;
    int t = threadIdx.x;

    const float* xb = g_xn + (size_t)(n*CDIM + g*CG)*SP;
    #pragma unroll
    for (int i = 0; i < 32; i++) {
        int idx = t + 256*i;
        xs[(idx>>6)*65 + (idx&63)] = xb[idx];
    }
    __syncthreads();

    int ts = t & 15, td = t >> 4;
    {
        float acc[4][4];
        #pragma unroll
        for (int i=0;i<4;i++)
            #pragma unroll
            for (int j=0;j<4;j++) acc[i][j]=0.f;
        const float* wb = wq + (size_t)(g*DH)*CG;
        #pragma unroll
        for (int kc = 0; kc < 128; kc += 64) {
            #pragma unroll
            for (int m = 0; m < 16; m++) {
                int idx = t + 256*m;
                ws[(idx>>6)*66 + (idx&63)] = wb[(idx>>6)*CG + kc + (idx&63)];
            }
            __syncthreads();
            for (int k = 0; k < 64; k++) {
                float wv4[4], xv[4];
                #pragma unroll
                for (int i=0;i<4;i++) { wv4[i]=ws[(td*4+i)*66 + k]; xv[i]=xs[(kc+k)*65 + ts*4+i]; }
                #pragma unroll
                for (int i=0;i<4;i++)
                    #pragma unroll
                    for (int j=0;j<4;j++) acc[i][j] = fmaf(wv4[i], xv[j], acc[i][j]);
            }
            __syncthreads();
        }
        #pragma unroll
        for (int i=0;i<4;i++)
            #pragma unroll
            for (int j=0;j<4;j++) qs[(td*4+i)*65 + ts*4+j] = acc[i][j];
    }
    __syncthreads();

    {
        int o = t >> 2, oi = t & 3, oy = oi >> 1, ox = oi & 1;
        float acc = ob1[o];
        #pragma unroll
        for (int ky=0;ky<6;ky++){
            int iy = 4*oy - 1 + ky;
            if (iy < 0 || iy > 7) continue;
            #pragma unroll
            for (int kx=0;kx<6;kx++){
                int ix = 4*ox - 1 + kx;
                if (ix < 0 || ix > 7) continue;
                acc = fmaf(qs[o*65 + iy*8+ix], ow1[o*36 + ky*6 + kx], acc);
            }
        }
        go[oi*64 + o] = 0.5f*acc*(1.f + erff(acc*0.70710678118654752f));
    }
    __syncthreads();
    if (t < 8) {
        int j = t >> 1, oo = t & 1;
        float s = 0.f;
        for (int c=0;c<64;c++) s = fmaf(go[j*64+c], ow2[oo*64+c], s);
        float off = tanhf(s)*4.0f;
        float base = (oo==0) ? (float)(j&1) : (float)(j>>1);
        float vg = 2.f*(base + off) - 1.f;
        vgr[j*2+oo] = vg;
        g_vgrid[(ng*4+j)*2+oo] = vg;
    }
    __syncthreads();
    if (t < 4) {
        float fx = ((vgr[t*2+0]+1.f)*8.f - 1.f)*0.5f;
        float fy = ((vgr[t*2+1]+1.f)*8.f - 1.f)*0.5f;
        float x0 = floorf(fx), y0 = floorf(fy);
        ip[t] = (int)x0; ip[4+t] = (int)y0;
        wxy[t] = fx - x0; wxy[4+t] = fy - y0;
    }
    __syncthreads();

    if (t < 128) {
        const float* img = xs + t*65;
        #pragma unroll
        for (int j=0;j<4;j++){
            int x0=ip[j], y0=ip[4+j];
            float wx1=wxy[j], wy1=wxy[4+j], wx0=1.f-wx1, wy0=1.f-wy1;
            bool xa = (x0>=0 && x0<8), xc = (x0+1>=0 && x0+1<8);
            bool ya = (y0>=0 && y0<8), yc = (y0+1>=0 && y0+1<8);
            float v00 = (xa&&ya)? img[y0*8+x0]       : 0.f;
            float v01 = (xc&&ya)? img[y0*8+x0+1]     : 0.f;
            float v10 = (xa&&yc)? img[(y0+1)*8+x0]   : 0.f;
            float v11 = (xc&&yc)? img[(y0+1)*8+x0+1] : 0.f;
            kvs[t*5+j] = v00*wx0*wy0 + v01*wx1*wy0 + v10*wx0*wy1 + v11*wx1*wy1;
        }
    }
    __syncthreads();

    int o4 = t >> 2, j4 = t & 3;
    {
        const float* wkb = wk + (size_t)g*DH*CG;
        const float* wvb = wv + (size_t)g*DH*CG;
        float ak = 0.f, av = 0.f;
        #pragma unroll
        for (int half = 0; half < 4; half++) {
            const float* wsrc = (half < 2) ? wkb : wvb;
            int ic = (half & 1) * 64;
            #pragma unroll
            for (int m = 0; m < 4; m++) {
                int fl4 = t + 256*m;
                int oL = fl4 >> 4, ii = (fl4 & 15) * 4;
                float4 v4 = *(const float4*)(wsrc + (size_t)oL*CG + ic + ii);
                ws[oL*66+ii] = v4.x; ws[oL*66+ii+1] = v4.y; ws[oL*66+ii+2] = v4.z; ws[oL*66+ii+3] = v4.w;
            }
            __syncthreads();
            float acc = 0.f;
            #pragma unroll 8
            for (int i = 0; i < 64; i++) acc = fmaf(kvs[(ic+i)*5 + j4], ws[o4*66+i], acc);
            if (half < 2) ak += acc; else av += acc;
            __syncthreads();
        }
        ksm[o4*5+j4] = ak;
        g_v[(size_t)(ng*DH+o4)*4+j4] = av;
    }
    __syncthreads();

    {
        int s4 = t >> 2;
        float a = 0.f;
        for (int d = 0; d < 64; d++) a = fmaf(qs[d*65+s4], ksm[d*5+j4], a);
        g_sim[(size_t)ng*256 + s4*4 + j4] = a*0.125f;
    }
}

// ---------------- K5: CPB MLP, fp16 mma m16n8k16; A recomputed in registers (R6 version) ----------------
__global__ __launch_bounds__(256,1) void k5_cpb_mma(const float* __restrict__ w1,
                                                    const float* __restrict__ b1,
                                                    const float* __restrict__ w2,
                                                    const float* __restrict__ b2,
                                                    const float* __restrict__ w3,
                                                    const float* __restrict__ b3) {
    __shared__ __half w2h[64*264];
    __shared__ float uu[512], vv[512];
    __shared__ float b2s[256], w3s[256];
    __shared__ float w1as[256], w1bs[256], b1s[256];

    int t = threadIdx.x;
    int lane = t & 31, w = t >> 5;
    int lq = lane >> 2, la3 = lane & 3;
    int r0 = w * 64;

    #pragma unroll
    for (int i = 0; i < 2; i++) {
        int rl = t + 256*i;
        int row = blockIdx.x*512 + rl;
        int ngi = row >> 8, p = row & 255;
        int s = p >> 2, j = p & 3;
        float qx = (float)(s & 7)*(2.f/7.f) - 1.f;
        float qy = (float)(s >> 3)*(2.f/7.f) - 1.f;
        float vx = g_vgrid[(ngi*4+j)*2+0];
        float vy = g_vgrid[(ngi*4+j)*2+1];
        float px = qx - vx, py = qy - vy;
        uu[rl] = copysignf(log1pf(fabsf(px)), px);
        vv[rl] = copysignf(log1pf(fabsf(py)), py);
    }
    b2s[t] = b2[t]; w3s[t] = w3[t];
    w1as[t] = w1[t]; w1bs[t] = w1[256+t]; b1s[t] = b1[t];
    __syncthreads();

    float ur[8], vr[8];
    #pragma unroll
    for (int j = 0; j < 8; j++) { ur[j] = uu[r0 + lq + 8*j]; vr[j] = vv[r0 + lq + 8*j]; }

    float accR[8];
    #pragma unroll
    for (int i = 0; i < 8; i++) accR[i] = 0.f;

    for (int ct = 0; ct < 4; ct++) {
        __syncthreads();
        #pragma unroll
        for (int i = 0; i < 32; i++) {
            int idx = t + 256*i;
            int nn = idx & 63, kp = idx >> 6;
            *(uint32_t*)&w2h[nn*264 + 2*kp] =
                pack2(w2[(2*kp)*256 + ct*64 + nn], w2[(2*kp+1)*256 + ct*64 + nn]);
        }
        __syncthreads();

        float C[4][8][4];
        #pragma unroll
        for (int mt=0;mt<4;mt++)
            #pragma unroll
            for (int nt=0;nt<8;nt++)
                #pragma unroll
                for (int i=0;i<4;i++) C[mt][nt][i]=0.f;

        #pragma unroll 1
        for (int ks = 0; ks < 16; ks++) {
            int k0 = ks*16 + 2*la3;
            float wa0 = w1as[k0],   wb0 = w1bs[k0],   bb0 = b1s[k0];
            float wa1 = w1as[k0+1], wb1 = w1bs[k0+1], bb1 = b1s[k0+1];
            float wa8 = w1as[k0+8], wb8 = w1bs[k0+8], bb8 = b1s[k0+8];
            float wa9 = w1as[k0+9], wb9 = w1bs[k0+9], bb9 = b1s[k0+9];
            uint32_t a[4][4];
            #pragma unroll
            for (int mt = 0; mt < 4; mt++) {
                float u0 = ur[2*mt],   v0 = vr[2*mt];
                float u1 = ur[2*mt+1], v1 = vr[2*mt+1];
                float h00 = fmaxf(fmaf(u0, wa0, fmaf(v0, wb0, bb0)), 0.f);
                float h01 = fmaxf(fmaf(u0, wa1, fmaf(v0, wb1, bb1)), 0.f);
                float h10 = fmaxf(fmaf(u1, wa0, fmaf(v1, wb0, bb0)), 0.f);
                float h11 = fmaxf(fmaf(u1, wa1, fmaf(v1, wb1, bb1)), 0.f);
                float h08 = fmaxf(fmaf(u0, wa8, fmaf(v0, wb8, bb8)), 0.f);
                float h09 = fmaxf(fmaf(u0, wa9, fmaf(v0, wb9, bb9)), 0.f);
                float h18 = fmaxf(fmaf(u1, wa8, fmaf(v1, wb8, bb8)), 0.f);
                float h19 = fmaxf(fmaf(u1, wa9, fmaf(v1, wb9, bb9)), 0.f);
                a[mt][0] = pack2(h00, h01);
                a[mt][1] = pack2(h10, h11);
                a[mt][2] = pack2(h08, h09);
                a[mt][3] = pack2(h18, h19);
            }
            #pragma unroll
            for (int nt = 0; nt < 8; nt++) {
                int nb = (nt*8 + lq)*264;
                uint32_t b0 = *(uint32_t*)&w2h[nb + k0];
                uint32_t b1v= *(uint32_t*)&w2h[nb + k0 + 8];
                #pragma unroll
                for (int mt = 0; mt < 4; mt++) {
                    asm volatile(
                        "mma.sync.aligned.m16n8k16.row.col.f32.f16.f16.f32 "
                        "{%0,%1,%2,%3}, {%4,%5,%6,%7}, {%8,%9}, {%0,%1,%2,%3};"
                        : "+f"(C[mt][nt][0]), "+f"(C[mt][nt][1]),
                          "+f"(C[mt][nt][2]), "+f"(C[mt][nt][3])
                        : "r"(a[mt][0]), "r"(a[mt][1]), "r"(a[mt][2]), "r"(a[mt][3]),
                          "r"(b0), "r"(b1v));
                }
            }
        }
        #pragma unroll
        for (int mt = 0; mt < 4; mt++)
            #pragma unroll
            for (int nt = 0; nt < 8; nt++) {
                int col = ct*64 + nt*8 + la3*2;
                float bb0 = b2s[col],   w30 = w3s[col];
                float bb1 = b2s[col+1], w31 = w3s[col+1];
                accR[mt*2+0] = fmaf(fmaxf(C[mt][nt][0]+bb0, 0.f), w30,
                               fmaf(fmaxf(C[mt][nt][1]+bb1, 0.f), w31, accR[mt*2+0]));
                accR[mt*2+1] = fmaf(fmaxf(C[mt][nt][2]+bb0, 0.f), w30,
                               fmaf(fmaxf(C[mt][nt][3]+bb1, 0.f), w31, accR[mt*2+1]));
            }
    }
    #pragma unroll
    for (int i = 0; i < 8; i++) {
        accR[i] += __shfl_xor_sync(0xffffffffu, accR[i], 1);
        accR[i] += __shfl_xor_sync(0xffffffffu, accR[i], 2);
    }
    if (la3 == 0) {
        float bz = b3[0];
        size_t base = (size_t)blockIdx.x*512 + r0;
        #pragma unroll
        for (int mt = 0; mt < 4; mt++) {
            g_bias[base + mt*16 + lq]     = accR[2*mt]   + bz;
            g_bias[base + mt*16 + 8 + lq] = accR[2*mt+1] + bz;
        }
    }
}

// ---------------- K6: softmax(4) + attn @ v (writes transposed ao [n][s][c]) ----------------
__global__ __launch_bounds__(256) void k6_av() {
    int ng = blockIdx.x; int n = ng >> 3, g = ng & 7;
    int t = threadIdx.x;
    __shared__ float att[64][5];
    __shared__ float vsm[64][5];
    {
        int s = t >> 2, j = t & 3;
        float e = g_sim[(size_t)ng*256 + t] + g_bias[(size_t)ng*256 + t];
        float m = e;
        m = fmaxf(m, __shfl_xor_sync(0xffffffffu, m, 1));
        m = fmaxf(m, __shfl_xor_sync(0xffffffffu, m, 2));
        float ex = __expf(e - m);
        float ssum = ex;
        ssum += __shfl_xor_sync(0xffffffffu, ssum, 1);
        ssum += __shfl_xor_sync(0xffffffffu, ssum, 2);
        att[s][j] = ex / ssum;
        vsm[s][j] = g_v[(size_t)ng*256 + t];
    }
    __syncthreads();
    int tsg = t >> 4, tdg = t & 15;
    float* ab = g_ao + (size_t)n*SP*512 + g*64;
    #pragma unroll
    for (int ss=0; ss<4; ss++) {
        int s = tsg*4 + ss;
        #pragma unroll
        for (int dd=0; dd<4; dd++) {
            int d = tdg*4 + dd;
            float a = att[s][0]*vsm[d][0] + att[s][1]*vsm[d][1]
                    + att[s][2]*vsm[d][2] + att[s][3]*vsm[d][3];
            ab[(size_t)s*512 + d] = a;
        }
    }
}

// ---------------- K7: final projection via fp16 mma + coalesced transposed stores ----------------
__global__ __launch_bounds__(256,2) void k7_out(const float* __restrict__ ow,
                                                const float* __restrict__ ob,
                                                float* __restrict__ out) {
    __shared__ __half a_h[128*40];
    __shared__ __half w_h[128*40];
    int bid = blockIdx.x;
    int m0 = (bid >> 3) * 128, n0 = (bid & 7) * 128;
    int t = threadIdx.x;
    int lane = t & 31, w = t >> 5;
    int lq = lane >> 2, la3 = lane & 3;
    int wm = (w >> 1) * 32, wn = (w & 1) * 64;

    float C[2][8][4];
    #pragma unroll
    for (int mt=0;mt<2;mt++)
        #pragma unroll
        for (int nt=0;nt<8;nt++)
            #pragma unroll
            for (int i=0;i<4;i++) C[mt][nt][i]=0.f;

    for (int kc = 0; kc < 16; kc++) {
        __syncthreads();
        #pragma unroll
        for (int i = 0; i < 4; i++) {
            int idx = t + 256*i;
            int row = idx >> 3, k4 = (idx & 7) * 4;
            float4 va = *(const float4*)(g_ao + (size_t)(m0+row)*512 + kc*32 + k4);
            *(uint32_t*)&a_h[row*40 + k4]     = pack2(va.x, va.y);
            *(uint32_t*)&a_h[row*40 + k4 + 2] = pack2(va.z, va.w);
            float4 vw = *(const float4*)(ow + (size_t)(n0+row)*512 + kc*32 + k4);
            *(uint32_t*)&w_h[row*40 + k4]     = pack2(vw.x, vw.y);
            *(uint32_t*)&w_h[row*40 + k4 + 2] = pack2(vw.z, vw.w);
        }
        __syncthreads();
        #pragma unroll
        for (int ks = 0; ks < 2; ks++) {
            int k0 = ks*16 + 2*la3;
            uint32_t a[2][4];
            #pragma unroll
            for (int mt = 0; mt < 2; mt++) {
                int ar = wm + mt*16 + lq;
                a[mt][0] = *(uint32_t*)&a_h[ar*40 + k0];
                a[mt][1] = *(uint32_t*)&a_h[(ar+8)*40 + k0];
                a[mt][2] = *(uint32_t*)&a_h[ar*40 + k0 + 8];
                a[mt][3] = *(uint32_t*)&a_h[(ar+8)*40 + k0 + 8];
            }
            #pragma unroll
            for (int nt = 0; nt < 8; nt++) {
                int br = wn + nt*8 + lq;
                uint32_t b0 = *(uint32_t*)&w_h[br*40 + k0];
                uint32_t b1v= *(uint32_t*)&w_h[br*40 + k0 + 8];
                #pragma unroll
                for (int mt = 0; mt < 2; mt++) {
                    asm volatile(
                        "mma.sync.aligned.m16n8k16.row.col.f32.f16.f16.f32 "
                        "{%0,%1,%2,%3}, {%4,%5,%6,%7}, {%8,%9}, {%0,%1,%2,%3};"
                        : "+f"(C[mt][nt][0]), "+f"(C[mt][nt][1]),
                          "+f"(C[mt][nt][2]), "+f"(C[mt][nt][3])
                        : "r"(a[mt][0]), "r"(a[mt][1]), "r"(a[mt][2]), "r"(a[mt][3]),
                          "r"(b0), "r"(b1v));
                }
            }
        }
    }

    // ---- coalesced epilogue: transpose 128x16 o-groups through smem ----
    float* buf = (float*)a_h;   // 16*132*4 = 8448 B <= 10240 B
    int wn_group = (w & 1) * 4; // this warp's og range start
    for (int og = 0; og < 8; og++) {
        __syncthreads();
        if ((og >> 2) == (w & 1)) {
            int ntb = (og - wn_group) * 2;
            #pragma unroll
            for (int nn = 0; nn < 2; nn++) {
                int nt = ntb + nn;
                int ol = nn*8 + 2*la3;
                #pragma unroll
                for (int mt = 0; mt < 2; mt++) {
                    int ml = wm + mt*16 + lq;
                    buf[ol*132 + ml]       = C[mt][nt][0];
                    buf[(ol+1)*132 + ml]   = C[mt][nt][1];
                    buf[ol*132 + ml + 8]   = C[mt][nt][2];
                    buf[(ol+1)*132 + ml+8] = C[mt][nt][3];
                }
            }
        }
        __syncthreads();
        {
            int o_l = t >> 4, mr = (t & 15) * 8;
            int o = n0 + og*16 + o_l;
            float obv = ob[o];
            int m = m0 + mr;
            int np = m >> 6, s = m & 63;
            int bi = np & 63, q = np >> 6;
            int Y = (q >> 1)*8 + (s >> 3);
            int X = (q & 1)*8;
            float* dst = out + (size_t)bi*262144 + o*256 + Y*16 + X;
            const float* src = buf + o_l*132 + mr;
            float4 v0, v1;
            v0.x = src[0]+obv; v0.y = src[1]+obv; v0.z = src[2]+obv; v0.w = src[3]+obv;
            v1.x = src[4]+obv; v1.y = src[5]+obv; v1.z = src[6]+obv; v1.w = src[7]+obv;
            *(float4*)dst = v0;
            *(float4*)(dst+4) = v1;
        }
    }
}

// ---------------- launch ----------------
extern "C" void kernel_launch(void* const* d_in, const int* in_sizes, int n_in,
                              void* d_out, int out_size) {
    const float* x      = (const float*)d_in[0];
    const float* ln_g   = (const float*)d_in[1];
    const float* ln_b   = (const float*)d_in[2];
    const float* wq     = (const float*)d_in[3];
    const float* wk     = (const float*)d_in[4];
    const float* wv     = (const float*)d_in[5];
    const float* off_w1 = (const float*)d_in[6];
    const float* off_b1 = (const float*)d_in[7];
    const float* off_w2 = (const float*)d_in[8];
    const float* cpb_w1 = (const float*)d_in[9];
    const float* cpb_b1 = (const float*)d_in[10];
    const float* cpb_w2 = (const float*)d_in[11];
    const float* cpb_b2 = (const float*)d_in[12];
    const float* cpb_w3 = (const float*)d_in[13];
    const float* cpb_b3 = (const float*)d_in[14];
    const float* out_w  = (const float*)d_in[15];
    const float* out_b  = (const float*)d_in[16];
    float* out = (float*)d_out;

    static int attr_done = 0;
    if (!attr_done) {
        cudaFuncSetAttribute(k234, cudaFuncAttributeMaxDynamicSharedMemorySize, K234_SMEM);
        attr_done = 1;
    }

    k1_ln     <<<1024, 256>>>(x, ln_g, ln_b);
    k234      <<<2048, 256, K234_SMEM>>>(wq, off_w1, off_b1, off_w2, wk, wv);
    k5_cpb_mma<<<1024, 256>>>(cpb_w1, cpb_b1, cpb_w2, cpb_b2, cpb_w3, cpb_b3);
    k6_av     <<<2048, 256>>>();
    k7_out    <<<1024, 256>>>(out_w, out_b, out);
}

// round 10
// speedup vs baseline: 1.0658x; 1.0454x over previous
#include <cuda_runtime.h>
#include <cuda_fp16.h>
#include <math.h>
#include <stdint.h>

#define NB     256
#define CDIM   1024
#define GROUPS 8
#define CG     128
#define DH     64
#define SP     64
#define NG     (NB*GROUPS)

// ---------------- scratch ----------------
__device__ float  g_xn[NB*CDIM*SP];
__device__ float  g_vgrid[NG*4*2];
__device__ float  g_v [NG*DH*4];
__device__ float  g_sim [NG*SP*4];
__device__ float  g_bias[NG*SP*4];
__device__ __half g_aoh[NB*SP*512];      // attention out TRANSPOSED, half: [n][s][c]
__device__ __half g_owh[1024*512];       // out_w pre-halved

__device__ __forceinline__ uint32_t pack2(float x, float y) {
    __half2 h = __floats2half2_rn(x, y);
    return *(uint32_t*)&h;
}
__device__ __forceinline__ uint32_t smem_u32(const void* p) {
    uint32_t a;
    asm("{ .reg .u64 t; cvta.to.shared.u64 t, %1; cvt.u32.u64 %0, t; }" : "=r"(a) : "l"(p));
    return a;
}
#define CP16(dst, src) asm volatile("cp.async.cg.shared.global [%0], [%1], 16;" :: "r"(dst), "l"(src))

// ---------------- K0w: out_w -> half ----------------
__global__ __launch_bounds__(256) void k0w(const float* __restrict__ ow) {
    int idx = (blockIdx.x*256 + threadIdx.x) * 4;
    float4 v = *(const float4*)(ow + idx);
    uint2 p;
    p.x = pack2(v.x, v.y);
    p.y = pack2(v.z, v.w);
    *(uint2*)&g_owh[idx] = p;
}

// ---------------- K1: LayerNorm + patchify ----------------
__global__ __launch_bounds__(256) void k1_ln(const float* __restrict__ x,
                                             const float* __restrict__ lng,
                                             const float* __restrict__ lnb) {
    int bid = blockIdx.x;
    int bi = bid >> 4, y = bid & 15;
    int t = threadIdx.x;
    int xcol = t & 15, ci = t >> 4;
    const float* px = x + (size_t)bi*CDIM*256 + y*16 + xcol;
    float s1 = 0.f, s2 = 0.f;
    for (int m = 0; m < 64; m++) {
        float v = px[(ci + 16*m)*256];
        s1 += v; s2 += v*v;
    }
    __shared__ float sm1[16][17], sm2[16][17];
    sm1[ci][xcol] = s1; sm2[ci][xcol] = s2;
    __syncthreads();
    for (int st = 8; st > 0; st >>= 1) {
        if (ci < st) { sm1[ci][xcol] += sm1[ci+st][xcol]; sm2[ci][xcol] += sm2[ci+st][xcol]; }
        __syncthreads();
    }
    float mu  = sm1[0][xcol] * (1.f/1024.f);
    float var = sm2[0][xcol] * (1.f/1024.f) - mu*mu;
    float rstd = rsqrtf(var + 1e-6f);
    int n = ((y>>3)*2 + (xcol>>3))*64 + bi;
    int s = (y&7)*8 + (xcol&7);
    float* po = g_xn + (size_t)n*CDIM*SP + s;
    for (int m = 0; m < 64; m++) {
        int c = ci + 16*m;
        float v = px[c*256];
        po[c*SP] = (v - mu)*rstd*lng[c] + lnb[c];
    }
}

// ---------------- K234: q proj + offsets + grid-sample + k/v proj + sim ----------------
#define K234_SMEM 72192
__global__ __launch_bounds__(256,1) void k234(const float* __restrict__ wq,
                                              const float* __restrict__ ow1,
                                              const float* __restrict__ ob1,
                                              const float* __restrict__ ow2,
                                              const float* __restrict__ wk,
                                              const float* __restrict__ wv) {
    extern __shared__ float sm[];
    float* xs  = sm;
    float* qs  = xs + 128*65;
    float* ws  = qs + 64*65;
    float* kvs = ws + 64*66;
    float* ksm = kvs + 128*5;
    float* go  = ksm + 64*5;
    float* vgr = go + 256;
    int*   ip  = (int*)(vgr + 8);
    float* wxy = (float*)(ip + 8);

    int ng = blockIdx.x; int n = ng >> 3, g = ng & 7;
    int t = threadIdx.x;

    const float* xb = g_xn + (size_t)(n*CDIM + g*CG)*SP;
    #pragma unroll
    for (int i = 0; i < 32; i++) {
        int idx = t + 256*i;
        xs[(idx>>6)*65 + (idx&63)] = xb[idx];
    }
    __syncthreads();

    int ts = t & 15, td = t >> 4;
    {
        float acc[4][4];
        #pragma unroll
        for (int i=0;i<4;i++)
            #pragma unroll
            for (int j=0;j<4;j++) acc[i][j]=0.f;
        const float* wb = wq + (size_t)(g*DH)*CG;
        #pragma unroll
        for (int kc = 0; kc < 128; kc += 64) {
            #pragma unroll
            for (int m = 0; m < 16; m++) {
                int idx = t + 256*m;
                ws[(idx>>6)*66 + (idx&63)] = wb[(idx>>6)*CG + kc + (idx&63)];
            }
            __syncthreads();
            for (int k = 0; k < 64; k++) {
                float wv4[4], xv[4];
                #pragma unroll
                for (int i=0;i<4;i++) { wv4[i]=ws[(td*4+i)*66 + k]; xv[i]=xs[(kc+k)*65 + ts*4+i]; }
                #pragma unroll
                for (int i=0;i<4;i++)
                    #pragma unroll
                    for (int j=0;j<4;j++) acc[i][j] = fmaf(wv4[i], xv[j], acc[i][j]);
            }
            __syncthreads();
        }
        #pragma unroll
        for (int i=0;i<4;i++)
            #pragma unroll
            for (int j=0;j<4;j++) qs[(td*4+i)*65 + ts*4+j] = acc[i][j];
    }
    __syncthreads();

    {
        int o = t >> 2, oi = t & 3, oy = oi >> 1, ox = oi & 1;
        float acc = ob1[o];
        #pragma unroll
        for (int ky=0;ky<6;ky++){
            int iy = 4*oy - 1 + ky;
            if (iy < 0 || iy > 7) continue;
            #pragma unroll
            for (int kx=0;kx<6;kx++){
                int ix = 4*ox - 1 + kx;
                if (ix < 0 || ix > 7) continue;
                acc = fmaf(qs[o*65 + iy*8+ix], ow1[o*36 + ky*6 + kx], acc);
            }
        }
        go[oi*64 + o] = 0.5f*acc*(1.f + erff(acc*0.70710678118654752f));
    }
    __syncthreads();
    if (t < 8) {
        int j = t >> 1, oo = t & 1;
        float s = 0.f;
        for (int c=0;c<64;c++) s = fmaf(go[j*64+c], ow2[oo*64+c], s);
        float off = tanhf(s)*4.0f;
        float base = (oo==0) ? (float)(j&1) : (float)(j>>1);
        float vg = 2.f*(base + off) - 1.f;
        vgr[j*2+oo] = vg;
        g_vgrid[(ng*4+j)*2+oo] = vg;
    }
    __syncthreads();
    if (t < 4) {
        float fx = ((vgr[t*2+0]+1.f)*8.f - 1.f)*0.5f;
        float fy = ((vgr[t*2+1]+1.f)*8.f - 1.f)*0.5f;
        float x0 = floorf(fx), y0 = floorf(fy);
        ip[t] = (int)x0; ip[4+t] = (int)y0;
        wxy[t] = fx - x0; wxy[4+t] = fy - y0;
    }
    __syncthreads();

    if (t < 128) {
        const float* img = xs + t*65;
        #pragma unroll
        for (int j=0;j<4;j++){
            int x0=ip[j], y0=ip[4+j];
            float wx1=wxy[j], wy1=wxy[4+j], wx0=1.f-wx1, wy0=1.f-wy1;
            bool xa = (x0>=0 && x0<8), xc = (x0+1>=0 && x0+1<8);
            bool ya = (y0>=0 && y0<8), yc = (y0+1>=0 && y0+1<8);
            float v00 = (xa&&ya)? img[y0*8+x0]       : 0.f;
            float v01 = (xc&&ya)? img[y0*8+x0+1]     : 0.f;
            float v10 = (xa&&yc)? img[(y0+1)*8+x0]   : 0.f;
            float v11 = (xc&&yc)? img[(y0+1)*8+x0+1] : 0.f;
            kvs[t*5+j] = v00*wx0*wy0 + v01*wx1*wy0 + v10*wx0*wy1 + v11*wx1*wy1;
        }
    }
    __syncthreads();

    int o4 = t >> 2, j4 = t & 3;
    {
        const float* wkb = wk + (size_t)g*DH*CG;
        const float* wvb = wv + (size_t)g*DH*CG;
        float ak = 0.f, av = 0.f;
        #pragma unroll
        for (int half = 0; half < 4; half++) {
            const float* wsrc = (half < 2) ? wkb : wvb;
            int ic = (half & 1) * 64;
            #pragma unroll
            for (int m = 0; m < 4; m++) {
                int fl4 = t + 256*m;
                int oL = fl4 >> 4, ii = (fl4 & 15) * 4;
                float4 v4 = *(const float4*)(wsrc + (size_t)oL*CG + ic + ii);
                ws[oL*66+ii] = v4.x; ws[oL*66+ii+1] = v4.y; ws[oL*66+ii+2] = v4.z; ws[oL*66+ii+3] = v4.w;
            }
            __syncthreads();
            float acc = 0.f;
            #pragma unroll 8
            for (int i = 0; i < 64; i++) acc = fmaf(kvs[(ic+i)*5 + j4], ws[o4*66+i], acc);
            if (half < 2) ak += acc; else av += acc;
            __syncthreads();
        }
        ksm[o4*5+j4] = ak;
        g_v[(size_t)(ng*DH+o4)*4+j4] = av;
    }
    __syncthreads();

    {
        int s4 = t >> 2;
        float a = 0.f;
        for (int d = 0; d < 64; d++) a = fmaf(qs[d*65+s4], ksm[d*5+j4], a);
        g_sim[(size_t)ng*256 + s4*4 + j4] = a*0.125f;
    }
}

// ---------------- K5: CPB MLP, fp16 mma m16n8k16 (R6-measured-good) ----------------
__global__ __launch_bounds__(256,1) void k5_cpb_mma(const float* __restrict__ w1,
                                                    const float* __restrict__ b1,
                                                    const float* __restrict__ w2,
                                                    const float* __restrict__ b2,
                                                    const float* __restrict__ w3,
                                                    const float* __restrict__ b3) {
    __shared__ __half w2h[64*264];
    __shared__ float uu[512], vv[512];
    __shared__ float b2s[256], w3s[256];
    __shared__ float w1as[256], w1bs[256], b1s[256];

    int t = threadIdx.x;
    int lane = t & 31, w = t >> 5;
    int lq = lane >> 2, la3 = lane & 3;
    int r0 = w * 64;

    #pragma unroll
    for (int i = 0; i < 2; i++) {
        int rl = t + 256*i;
        int row = blockIdx.x*512 + rl;
        int ngi = row >> 8, p = row & 255;
        int s = p >> 2, j = p & 3;
        float qx = (float)(s & 7)*(2.f/7.f) - 1.f;
        float qy = (float)(s >> 3)*(2.f/7.f) - 1.f;
        float vx = g_vgrid[(ngi*4+j)*2+0];
        float vy = g_vgrid[(ngi*4+j)*2+1];
        float px = qx - vx, py = qy - vy;
        uu[rl] = copysignf(log1pf(fabsf(px)), px);
        vv[rl] = copysignf(log1pf(fabsf(py)), py);
    }
    b2s[t] = b2[t]; w3s[t] = w3[t];
    w1as[t] = w1[t]; w1bs[t] = w1[256+t]; b1s[t] = b1[t];
    __syncthreads();

    float ur[8], vr[8];
    #pragma unroll
    for (int j = 0; j < 8; j++) { ur[j] = uu[r0 + lq + 8*j]; vr[j] = vv[r0 + lq + 8*j]; }

    float accR[8];
    #pragma unroll
    for (int i = 0; i < 8; i++) accR[i] = 0.f;

    for (int ct = 0; ct < 4; ct++) {
        __syncthreads();
        #pragma unroll
        for (int i = 0; i < 32; i++) {
            int idx = t + 256*i;
            int nn = idx & 63, kp = idx >> 6;
            *(uint32_t*)&w2h[nn*264 + 2*kp] =
                pack2(w2[(2*kp)*256 + ct*64 + nn], w2[(2*kp+1)*256 + ct*64 + nn]);
        }
        __syncthreads();

        float C[4][8][4];
        #pragma unroll
        for (int mt=0;mt<4;mt++)
            #pragma unroll
            for (int nt=0;nt<8;nt++)
                #pragma unroll
                for (int i=0;i<4;i++) C[mt][nt][i]=0.f;

        #pragma unroll 1
        for (int ks = 0; ks < 16; ks++) {
            int k0 = ks*16 + 2*la3;
            float wa0 = w1as[k0],   wb0 = w1bs[k0],   bb0 = b1s[k0];
            float wa1 = w1as[k0+1], wb1 = w1bs[k0+1], bb1 = b1s[k0+1];
            float wa8 = w1as[k0+8], wb8 = w1bs[k0+8], bb8 = b1s[k0+8];
            float wa9 = w1as[k0+9], wb9 = w1bs[k0+9], bb9 = b1s[k0+9];
            uint32_t a[4][4];
            #pragma unroll
            for (int mt = 0; mt < 4; mt++) {
                float u0 = ur[2*mt],   v0 = vr[2*mt];
                float u1 = ur[2*mt+1], v1 = vr[2*mt+1];
                float h00 = fmaxf(fmaf(u0, wa0, fmaf(v0, wb0, bb0)), 0.f);
                float h01 = fmaxf(fmaf(u0, wa1, fmaf(v0, wb1, bb1)), 0.f);
                float h10 = fmaxf(fmaf(u1, wa0, fmaf(v1, wb0, bb0)), 0.f);
                float h11 = fmaxf(fmaf(u1, wa1, fmaf(v1, wb1, bb1)), 0.f);
                float h08 = fmaxf(fmaf(u0, wa8, fmaf(v0, wb8, bb8)), 0.f);
                float h09 = fmaxf(fmaf(u0, wa9, fmaf(v0, wb9, bb9)), 0.f);
                float h18 = fmaxf(fmaf(u1, wa8, fmaf(v1, wb8, bb8)), 0.f);
                float h19 = fmaxf(fmaf(u1, wa9, fmaf(v1, wb9, bb9)), 0.f);
                a[mt][0] = pack2(h00, h01);
                a[mt][1] = pack2(h10, h11);
                a[mt][2] = pack2(h08, h09);
                a[mt][3] = pack2(h18, h19);
            }
            #pragma unroll
            for (int nt = 0; nt < 8; nt++) {
                int nb = (nt*8 + lq)*264;
                uint32_t b0 = *(uint32_t*)&w2h[nb + k0];
                uint32_t b1v= *(uint32_t*)&w2h[nb + k0 + 8];
                #pragma unroll
                for (int mt = 0; mt < 4; mt++) {
                    asm volatile(
                        "mma.sync.aligned.m16n8k16.row.col.f32.f16.f16.f32 "
                        "{%0,%1,%2,%3}, {%4,%5,%6,%7}, {%8,%9}, {%0,%1,%2,%3};"
                        : "+f"(C[mt][nt][0]), "+f"(C[mt][nt][1]),
                          "+f"(C[mt][nt][2]), "+f"(C[mt][nt][3])
                        : "r"(a[mt][0]), "r"(a[mt][1]), "r"(a[mt][2]), "r"(a[mt][3]),
                          "r"(b0), "r"(b1v));
                }
            }
        }
        #pragma unroll
        for (int mt = 0; mt < 4; mt++)
            #pragma unroll
            for (int nt = 0; nt < 8; nt++) {
                int col = ct*64 + nt*8 + la3*2;
                float bb0 = b2s[col],   w30 = w3s[col];
                float bb1 = b2s[col+1], w31 = w3s[col+1];
                accR[mt*2+0] = fmaf(fmaxf(C[mt][nt][0]+bb0, 0.f), w30,
                               fmaf(fmaxf(C[mt][nt][1]+bb1, 0.f), w31, accR[mt*2+0]));
                accR[mt*2+1] = fmaf(fmaxf(C[mt][nt][2]+bb0, 0.f), w30,
                               fmaf(fmaxf(C[mt][nt][3]+bb1, 0.f), w31, accR[mt*2+1]));
            }
    }
    #pragma unroll
    for (int i = 0; i < 8; i++) {
        accR[i] += __shfl_xor_sync(0xffffffffu, accR[i], 1);
        accR[i] += __shfl_xor_sync(0xffffffffu, accR[i], 2);
    }
    if (la3 == 0) {
        float bz = b3[0];
        size_t base = (size_t)blockIdx.x*512 + r0;
        #pragma unroll
        for (int mt = 0; mt < 4; mt++) {
            g_bias[base + mt*16 + lq]     = accR[2*mt]   + bz;
            g_bias[base + mt*16 + 8 + lq] = accR[2*mt+1] + bz;
        }
    }
}

// ---------------- K6: softmax(4) + attn @ v (writes HALF transposed ao) ----------------
__global__ __launch_bounds__(256) void k6_av() {
    int ng = blockIdx.x; int n = ng >> 3, g = ng & 7;
    int t = threadIdx.x;
    __shared__ float att[64][5];
    __shared__ float vsm[64][5];
    {
        int s = t >> 2, j = t & 3;
        float e = g_sim[(size_t)ng*256 + t] + g_bias[(size_t)ng*256 + t];
        float m = e;
        m = fmaxf(m, __shfl_xor_sync(0xffffffffu, m, 1));
        m = fmaxf(m, __shfl_xor_sync(0xffffffffu, m, 2));
        float ex = __expf(e - m);
        float ssum = ex;
        ssum += __shfl_xor_sync(0xffffffffu, ssum, 1);
        ssum += __shfl_xor_sync(0xffffffffu, ssum, 2);
        att[s][j] = ex / ssum;
        vsm[s][j] = g_v[(size_t)ng*256 + t];
    }
    __syncthreads();
    int tsg = t >> 4, tdg = t & 15;
    __half* ab = g_aoh + (size_t)n*SP*512 + g*64;
    #pragma unroll
    for (int ss=0; ss<4; ss++) {
        int s = tsg*4 + ss;
        float av[4];
        #pragma unroll
        for (int dd=0; dd<4; dd++) {
            int d = tdg*4 + dd;
            av[dd] = att[s][0]*vsm[d][0] + att[s][1]*vsm[d][1]
                   + att[s][2]*vsm[d][2] + att[s][3]*vsm[d][3];
        }
        uint2 p;
        p.x = pack2(av[0], av[1]);
        p.y = pack2(av[2], av[3]);
        *(uint2*)(ab + (size_t)s*512 + tdg*4) = p;
    }
}

// ---------------- K7: final projection; half operands + cp.async double buffer ----------------
__global__ __launch_bounds__(256,2) void k7_out(const float* __restrict__ ob,
                                                float* __restrict__ out) {
    __shared__ __half a_h[2][128*40];
    __shared__ __half w_h[2][128*40];
    int bid = blockIdx.x;
    int m0 = (bid >> 3) * 128, n0 = (bid & 7) * 128;
    int t = threadIdx.x;
    int lane = t & 31, w = t >> 5;
    int lq = lane >> 2, la3 = lane & 3;
    int wm = (w >> 1) * 32, wn = (w & 1) * 64;

    uint32_t abase[2] = { smem_u32(a_h[0]), smem_u32(a_h[1]) };
    uint32_t wbase[2] = { smem_u32(w_h[0]), smem_u32(w_h[1]) };
    int lrow = t >> 2, lc4 = (t & 3) * 16;   // each thread: 1 row, one 16B chunk per half-tile pass

    // per-thread load job: rows lrow and lrow+64 (2 chunks each of the 4 per row? No:
    // 128 rows x 4 chunks = 512 chunks per tile; 256 threads -> 2 chunks each.
    // thread covers (row = t>>1, chunk = (t&1)*2 + i) i in {0,1}
    auto issue_loads = [&](int kc, int b) {
        int row = t >> 1;
        int cbase = (t & 1) * 2;
        #pragma unroll
        for (int i = 0; i < 2; i++) {
            int c4 = cbase + i;                      // 0..3, 8 halves each
            uint32_t da = abase[b] + row*80 + c4*16;
            const __half* sa = g_aoh + (size_t)(m0+row)*512 + kc*32 + c4*8;
            CP16(da, sa);
            uint32_t dw = wbase[b] + row*80 + c4*16;
            const __half* sw = g_owh + (size_t)(n0+row)*512 + kc*32 + c4*8;
            CP16(dw, sw);
        }
        asm volatile("cp.async.commit_group;");
    };

    float C[2][8][4];
    #pragma unroll
    for (int mt=0;mt<2;mt++)
        #pragma unroll
        for (int nt=0;nt<8;nt++)
            #pragma unroll
            for (int i=0;i<4;i++) C[mt][nt][i]=0.f;

    issue_loads(0, 0);
    for (int kc = 0; kc < 16; kc++) {
        int b = kc & 1;
        if (kc < 15) {
            issue_loads(kc+1, b^1);
            asm volatile("cp.async.wait_group 1;");
        } else {
            asm volatile("cp.async.wait_group 0;");
        }
        __syncthreads();
        #pragma unroll
        for (int ks = 0; ks < 2; ks++) {
            int k0 = ks*16 + 2*la3;
            uint32_t a[2][4];
            #pragma unroll
            for (int mt = 0; mt < 2; mt++) {
                int ar = wm + mt*16 + lq;
                a[mt][0] = *(uint32_t*)&a_h[b][ar*40 + k0];
                a[mt][1] = *(uint32_t*)&a_h[b][(ar+8)*40 + k0];
                a[mt][2] = *(uint32_t*)&a_h[b][ar*40 + k0 + 8];
                a[mt][3] = *(uint32_t*)&a_h[b][(ar+8)*40 + k0 + 8];
            }
            #pragma unroll
            for (int nt = 0; nt < 8; nt++) {
                int br = wn + nt*8 + lq;
                uint32_t b0 = *(uint32_t*)&w_h[b][br*40 + k0];
                uint32_t b1v= *(uint32_t*)&w_h[b][br*40 + k0 + 8];
                #pragma unroll
                for (int mt = 0; mt < 2; mt++) {
                    asm volatile(
                        "mma.sync.aligned.m16n8k16.row.col.f32.f16.f16.f32 "
                        "{%0,%1,%2,%3}, {%4,%5,%6,%7}, {%8,%9}, {%0,%1,%2,%3};"
                        : "+f"(C[mt][nt][0]), "+f"(C[mt][nt][1]),
                          "+f"(C[mt][nt][2]), "+f"(C[mt][nt][3])
                        : "r"(a[mt][0]), "r"(a[mt][1]), "r"(a[mt][2]), "r"(a[mt][3]),
                          "r"(b0), "r"(b1v));
                }
            }
        }
        __syncthreads();
    }

    // ---- coalesced epilogue: transpose 128x16 o-groups through smem ----
    float* buf = (float*)a_h;   // 16*132*4 = 8448 B
    int wn_group = (w & 1) * 4;
    for (int og = 0; og < 8; og++) {
        __syncthreads();
        if ((og >> 2) == (w & 1)) {
            int ntb = (og - wn_group) * 2;
            #pragma unroll
            for (int nn = 0; nn < 2; nn++) {
                int nt = ntb + nn;
                int ol = nn*8 + 2*la3;
                #pragma unroll
                for (int mt = 0; mt < 2; mt++) {
                    int ml = wm + mt*16 + lq;
                    buf[ol*132 + ml]       = C[mt][nt][0];
                    buf[(ol+1)*132 + ml]   = C[mt][nt][1];
                    buf[ol*132 + ml + 8]   = C[mt][nt][2];
                    buf[(ol+1)*132 + ml+8] = C[mt][nt][3];
                }
            }
        }
        __syncthreads();
        {
            int o_l = t >> 4, mr = (t & 15) * 8;
            int o = n0 + og*16 + o_l;
            float obv = ob[o];
            int m = m0 + mr;
            int np = m >> 6, s = m & 63;
            int bi = np & 63, q = np >> 6;
            int Y = (q >> 1)*8 + (s >> 3);
            int X = (q & 1)*8;
            float* dst = out + (size_t)bi*262144 + o*256 + Y*16 + X;
            const float* src = buf + o_l*132 + mr;
            float4 v0, v1;
            v0.x = src[0]+obv; v0.y = src[1]+obv; v0.z = src[2]+obv; v0.w = src[3]+obv;
            v1.x = src[4]+obv; v1.y = src[5]+obv; v1.z = src[6]+obv; v1.w = src[7]+obv;
            *(float4*)dst = v0;
            *(float4*)(dst+4) = v1;
        }
    }
}

// ---------------- launch ----------------
extern "C" void kernel_launch(void* const* d_in, const int* in_sizes, int n_in,
                              void* d_out, int out_size) {
    const float* x      = (const float*)d_in[0];
    const float* ln_g   = (const float*)d_in[1];
    const float* ln_b   = (const float*)d_in[2];
    const float* wq     = (const float*)d_in[3];
    const float* wk     = (const float*)d_in[4];
    const float* wv     = (const float*)d_in[5];
    const float* off_w1 = (const float*)d_in[6];
    const float* off_b1 = (const float*)d_in[7];
    const float* off_w2 = (const float*)d_in[8];
    const float* cpb_w1 = (const float*)d_in[9];
    const float* cpb_b1 = (const float*)d_in[10];
    const float* cpb_w2 = (const float*)d_in[11];
    const float* cpb_b2 = (const float*)d_in[12];
    const float* cpb_w3 = (const float*)d_in[13];
    const float* cpb_b3 = (const float*)d_in[14];
    const float* out_w  = (const float*)d_in[15];
    const float* out_b  = (const float*)d_in[16];
    float* out = (float*)d_out;

    static int attr_done = 0;
    if (!attr_done) {
        cudaFuncSetAttribute(k234, cudaFuncAttributeMaxDynamicSharedMemorySize, K234_SMEM);
        attr_done = 1;
    }

    k0w       <<<512, 256>>>(out_w);
    k1_ln     <<<1024, 256>>>(x, ln_g, ln_b);
    k234      <<<2048, 256, K234_SMEM>>>(wq, off_w1, off_b1, off_w2, wk, wv);
    k5_cpb_mma<<<1024, 256>>>(cpb_w1, cpb_b1, cpb_w2, cpb_b2, cpb_w3, cpb_b3);
    k6_av     <<<2048, 256>>>();
    k7_out    <<<1024, 256>>>(out_b, out);
}

// round 11
// speedup vs baseline: 1.0677x; 1.0018x over previous
#include <cuda_runtime.h>
#include <cuda_fp16.h>
#include <math.h>
#include <stdint.h>

#define NB     256
#define CDIM   1024
#define GROUPS 8
#define CG     128
#define DH     64
#define SP     64
#define NG     (NB*GROUPS)

// ---------------- scratch ----------------
__device__ float  g_xn[NB*CDIM*SP];
__device__ float  g_vgrid[NG*4*2];
__device__ float  g_v [NG*DH*4];
__device__ float  g_sim [NG*SP*4];
__device__ float  g_bias[NG*SP*4];
__device__ __half g_aoh[NB*SP*512];      // attention out TRANSPOSED, half: [n][s][c]
__device__ __half g_owh[1024*512];       // out_w pre-halved

__device__ __forceinline__ uint32_t pack2(float x, float y) {
    __half2 h = __floats2half2_rn(x, y);
    return *(uint32_t*)&h;
}
__device__ __forceinline__ uint32_t smem_u32(const void* p) {
    uint32_t a;
    asm("{ .reg .u64 t; cvta.to.shared.u64 t, %1; cvt.u32.u64 %0, t; }" : "=r"(a) : "l"(p));
    return a;
}
#define CP16(dst, src) asm volatile("cp.async.cg.shared.global [%0], [%1], 16;" :: "r"(dst), "l"(src))

// ---------------- K0w: out_w -> half ----------------
__global__ __launch_bounds__(256) void k0w(const float* __restrict__ ow) {
    int idx = (blockIdx.x*256 + threadIdx.x) * 4;
    float4 v = *(const float4*)(ow + idx);
    uint2 p;
    p.x = pack2(v.x, v.y);
    p.y = pack2(v.z, v.w);
    *(uint2*)&g_owh[idx] = p;
}

// ---------------- K1: LayerNorm + patchify ----------------
__global__ __launch_bounds__(256) void k1_ln(const float* __restrict__ x,
                                             const float* __restrict__ lng,
                                             const float* __restrict__ lnb) {
    int bid = blockIdx.x;
    int bi = bid >> 4, y = bid & 15;
    int t = threadIdx.x;
    int xcol = t & 15, ci = t >> 4;
    const float* px = x + (size_t)bi*CDIM*256 + y*16 + xcol;
    float s1 = 0.f, s2 = 0.f;
    for (int m = 0; m < 64; m++) {
        float v = px[(ci + 16*m)*256];
        s1 += v; s2 += v*v;
    }
    __shared__ float sm1[16][17], sm2[16][17];
    sm1[ci][xcol] = s1; sm2[ci][xcol] = s2;
    __syncthreads();
    for (int st = 8; st > 0; st >>= 1) {
        if (ci < st) { sm1[ci][xcol] += sm1[ci+st][xcol]; sm2[ci][xcol] += sm2[ci+st][xcol]; }
        __syncthreads();
    }
    float mu  = sm1[0][xcol] * (1.f/1024.f);
    float var = sm2[0][xcol] * (1.f/1024.f) - mu*mu;
    float rstd = rsqrtf(var + 1e-6f);
    int n = ((y>>3)*2 + (xcol>>3))*64 + bi;
    int s = (y&7)*8 + (xcol&7);
    float* po = g_xn + (size_t)n*CDIM*SP + s;
    for (int m = 0; m < 64; m++) {
        int c = ci + 16*m;
        float v = px[c*256];
        po[c*SP] = (v - mu)*rstd*lng[c] + lnb[c];
    }
}

// ---------------- K234: q proj + offsets + grid-sample + k/v proj + sim ----------------
#define K234_SMEM 72192
__global__ __launch_bounds__(256,1) void k234(const float* __restrict__ wq,
                                              const float* __restrict__ ow1,
                                              const float* __restrict__ ob1,
                                              const float* __restrict__ ow2,
                                              const float* __restrict__ wk,
                                              const float* __restrict__ wv) {
    extern __shared__ float sm[];
    float* xs  = sm;
    float* qs  = xs + 128*65;
    float* ws  = qs + 64*65;
    float* kvs = ws + 64*66;
    float* ksm = kvs + 128*5;
    float* go  = ksm + 64*5;
    float* vgr = go + 256;
    int*   ip  = (int*)(vgr + 8);
    float* wxy = (float*)(ip + 8);

    int ng = blockIdx.x; int n = ng >> 3, g = ng & 7;
    int t = threadIdx.x;

    const float* xb = g_xn + (size_t)(n*CDIM + g*CG)*SP;
    #pragma unroll
    for (int i = 0; i < 32; i++) {
        int idx = t + 256*i;
        xs[(idx>>6)*65 + (idx&63)] = xb[idx];
    }
    __syncthreads();

    int ts = t & 15, td = t >> 4;
    {
        float acc[4][4];
        #pragma unroll
        for (int i=0;i<4;i++)
            #pragma unroll
            for (int j=0;j<4;j++) acc[i][j]=0.f;
        const float* wb = wq + (size_t)(g*DH)*CG;
        #pragma unroll
        for (int kc = 0; kc < 128; kc += 64) {
            #pragma unroll
            for (int m = 0; m < 16; m++) {
                int idx = t + 256*m;
                ws[(idx>>6)*66 + (idx&63)] = wb[(idx>>6)*CG + kc + (idx&63)];
            }
            __syncthreads();
            for (int k = 0; k < 64; k++) {
                float wv4[4], xv[4];
                #pragma unroll
                for (int i=0;i<4;i++) { wv4[i]=ws[(td*4+i)*66 + k]; xv[i]=xs[(kc+k)*65 + ts*4+i]; }
                #pragma unroll
                for (int i=0;i<4;i++)
                    #pragma unroll
                    for (int j=0;j<4;j++) acc[i][j] = fmaf(wv4[i], xv[j], acc[i][j]);
            }
            __syncthreads();
        }
        #pragma unroll
        for (int i=0;i<4;i++)
            #pragma unroll
            for (int j=0;j<4;j++) qs[(td*4+i)*65 + ts*4+j] = acc[i][j];
    }
    __syncthreads();

    {
        int o = t >> 2, oi = t & 3, oy = oi >> 1, ox = oi & 1;
        float acc = ob1[o];
        #pragma unroll
        for (int ky=0;ky<6;ky++){
            int iy = 4*oy - 1 + ky;
            if (iy < 0 || iy > 7) continue;
            #pragma unroll
            for (int kx=0;kx<6;kx++){
                int ix = 4*ox - 1 + kx;
                if (ix < 0 || ix > 7) continue;
                acc = fmaf(qs[o*65 + iy*8+ix], ow1[o*36 + ky*6 + kx], acc);
            }
        }
        go[oi*64 + o] = 0.5f*acc*(1.f + erff(acc*0.70710678118654752f));
    }
    __syncthreads();
    if (t < 8) {
        int j = t >> 1, oo = t & 1;
        float s = 0.f;
        for (int c=0;c<64;c++) s = fmaf(go[j*64+c], ow2[oo*64+c], s);
        float off = tanhf(s)*4.0f;
        float base = (oo==0) ? (float)(j&1) : (float)(j>>1);
        float vg = 2.f*(base + off) - 1.f;
        vgr[j*2+oo] = vg;
        g_vgrid[(ng*4+j)*2+oo] = vg;
    }
    __syncthreads();
    if (t < 4) {
        float fx = ((vgr[t*2+0]+1.f)*8.f - 1.f)*0.5f;
        float fy = ((vgr[t*2+1]+1.f)*8.f - 1.f)*0.5f;
        float x0 = floorf(fx), y0 = floorf(fy);
        ip[t] = (int)x0; ip[4+t] = (int)y0;
        wxy[t] = fx - x0; wxy[4+t] = fy - y0;
    }
    __syncthreads();

    if (t < 128) {
        const float* img = xs + t*65;
        #pragma unroll
        for (int j=0;j<4;j++){
            int x0=ip[j], y0=ip[4+j];
            float wx1=wxy[j], wy1=wxy[4+j], wx0=1.f-wx1, wy0=1.f-wy1;
            bool xa = (x0>=0 && x0<8), xc = (x0+1>=0 && x0+1<8);
            bool ya = (y0>=0 && y0<8), yc = (y0+1>=0 && y0+1<8);
            float v00 = (xa&&ya)? img[y0*8+x0]       : 0.f;
            float v01 = (xc&&ya)? img[y0*8+x0+1]     : 0.f;
            float v10 = (xa&&yc)? img[(y0+1)*8+x0]   : 0.f;
            float v11 = (xc&&yc)? img[(y0+1)*8+x0+1] : 0.f;
            kvs[t*5+j] = v00*wx0*wy0 + v01*wx1*wy0 + v10*wx0*wy1 + v11*wx1*wy1;
        }
    }
    __syncthreads();

    int o4 = t >> 2, j4 = t & 3;
    {
        const float* wkb = wk + (size_t)g*DH*CG;
        const float* wvb = wv + (size_t)g*DH*CG;
        float ak = 0.f, av = 0.f;
        #pragma unroll
        for (int half = 0; half < 4; half++) {
            const float* wsrc = (half < 2) ? wkb : wvb;
            int ic = (half & 1) * 64;
            #pragma unroll
            for (int m = 0; m < 4; m++) {
                int fl4 = t + 256*m;
                int oL = fl4 >> 4, ii = (fl4 & 15) * 4;
                float4 v4 = *(const float4*)(wsrc + (size_t)oL*CG + ic + ii);
                ws[oL*66+ii] = v4.x; ws[oL*66+ii+1] = v4.y; ws[oL*66+ii+2] = v4.z; ws[oL*66+ii+3] = v4.w;
            }
            __syncthreads();
            float acc = 0.f;
            #pragma unroll 8
            for (int i = 0; i < 64; i++) acc = fmaf(kvs[(ic+i)*5 + j4], ws[o4*66+i], acc);
            if (half < 2) ak += acc; else av += acc;
            __syncthreads();
        }
        ksm[o4*5+j4] = ak;
        g_v[(size_t)(ng*DH+o4)*4+j4] = av;
    }
    __syncthreads();

    {
        int s4 = t >> 2;
        float a = 0.f;
        for (int d = 0; d < 64; d++) a = fmaf(qs[d*65+s4], ksm[d*5+j4], a);
        g_sim[(size_t)ng*256 + s4*4 + j4] = a*0.125f;
    }
}

// ---------------- K5: CPB MLP, fp16 mma m16n8k16 (R6-measured-good) ----------------
__global__ __launch_bounds__(256,1) void k5_cpb_mma(const float* __restrict__ w1,
                                                    const float* __restrict__ b1,
                                                    const float* __restrict__ w2,
                                                    const float* __restrict__ b2,
                                                    const float* __restrict__ w3,
                                                    const float* __restrict__ b3) {
    __shared__ __half w2h[64*264];
    __shared__ float uu[512], vv[512];
    __shared__ float b2s[256], w3s[256];
    __shared__ float w1as[256], w1bs[256], b1s[256];

    int t = threadIdx.x;
    int lane = t & 31, w = t >> 5;
    int lq = lane >> 2, la3 = lane & 3;
    int r0 = w * 64;

    #pragma unroll
    for (int i = 0; i < 2; i++) {
        int rl = t + 256*i;
        int row = blockIdx.x*512 + rl;
        int ngi = row >> 8, p = row & 255;
        int s = p >> 2, j = p & 3;
        float qx = (float)(s & 7)*(2.f/7.f) - 1.f;
        float qy = (float)(s >> 3)*(2.f/7.f) - 1.f;
        float vx = g_vgrid[(ngi*4+j)*2+0];
        float vy = g_vgrid[(ngi*4+j)*2+1];
        float px = qx - vx, py = qy - vy;
        uu[rl] = copysignf(log1pf(fabsf(px)), px);
        vv[rl] = copysignf(log1pf(fabsf(py)), py);
    }
    b2s[t] = b2[t]; w3s[t] = w3[t];
    w1as[t] = w1[t]; w1bs[t] = w1[256+t]; b1s[t] = b1[t];
    __syncthreads();

    float ur[8], vr[8];
    #pragma unroll
    for (int j = 0; j < 8; j++) { ur[j] = uu[r0 + lq + 8*j]; vr[j] = vv[r0 + lq + 8*j]; }

    float accR[8];
    #pragma unroll
    for (int i = 0; i < 8; i++) accR[i] = 0.f;

    for (int ct = 0; ct < 4; ct++) {
        __syncthreads();
        #pragma unroll
        for (int i = 0; i < 32; i++) {
            int idx = t + 256*i;
            int nn = idx & 63, kp = idx >> 6;
            *(uint32_t*)&w2h[nn*264 + 2*kp] =
                pack2(w2[(2*kp)*256 + ct*64 + nn], w2[(2*kp+1)*256 + ct*64 + nn]);
        }
        __syncthreads();

        float C[4][8][4];
        #pragma unroll
        for (int mt=0;mt<4;mt++)
            #pragma unroll
            for (int nt=0;nt<8;nt++)
                #pragma unroll
                for (int i=0;i<4;i++) C[mt][nt][i]=0.f;

        #pragma unroll 1
        for (int ks = 0; ks < 16; ks++) {
            int k0 = ks*16 + 2*la3;
            float wa0 = w1as[k0],   wb0 = w1bs[k0],   bb0 = b1s[k0];
            float wa1 = w1as[k0+1], wb1 = w1bs[k0+1], bb1 = b1s[k0+1];
            float wa8 = w1as[k0+8], wb8 = w1bs[k0+8], bb8 = b1s[k0+8];
            float wa9 = w1as[k0+9], wb9 = w1bs[k0+9], bb9 = b1s[k0+9];
            uint32_t a[4][4];
            #pragma unroll
            for (int mt = 0; mt < 4; mt++) {
                float u0 = ur[2*mt],   v0 = vr[2*mt];
                float u1 = ur[2*mt+1], v1 = vr[2*mt+1];
                float h00 = fmaxf(fmaf(u0, wa0, fmaf(v0, wb0, bb0)), 0.f);
                float h01 = fmaxf(fmaf(u0, wa1, fmaf(v0, wb1, bb1)), 0.f);
                float h10 = fmaxf(fmaf(u1, wa0, fmaf(v1, wb0, bb0)), 0.f);
                float h11 = fmaxf(fmaf(u1, wa1, fmaf(v1, wb1, bb1)), 0.f);
                float h08 = fmaxf(fmaf(u0, wa8, fmaf(v0, wb8, bb8)), 0.f);
                float h09 = fmaxf(fmaf(u0, wa9, fmaf(v0, wb9, bb9)), 0.f);
                float h18 = fmaxf(fmaf(u1, wa8, fmaf(v1, wb8, bb8)), 0.f);
                float h19 = fmaxf(fmaf(u1, wa9, fmaf(v1, wb9, bb9)), 0.f);
                a[mt][0] = pack2(h00, h01);
                a[mt][1] = pack2(h10, h11);
                a[mt][2] = pack2(h08, h09);
                a[mt][3] = pack2(h18, h19);
            }
            #pragma unroll
            for (int nt = 0; nt < 8; nt++) {
                int nb = (nt*8 + lq)*264;
                uint32_t b0 = *(uint32_t*)&w2h[nb + k0];
                uint32_t b1v= *(uint32_t*)&w2h[nb + k0 + 8];
                #pragma unroll
                for (int mt = 0; mt < 4; mt++) {
                    asm volatile(
                        "mma.sync.aligned.m16n8k16.row.col.f32.f16.f16.f32 "
                        "{%0,%1,%2,%3}, {%4,%5,%6,%7}, {%8,%9}, {%0,%1,%2,%3};"
                        : "+f"(C[mt][nt][0]), "+f"(C[mt][nt][1]),
                          "+f"(C[mt][nt][2]), "+f"(C[mt][nt][3])
                        : "r"(a[mt][0]), "r"(a[mt][1]), "r"(a[mt][2]), "r"(a[mt][3]),
                          "r"(b0), "r"(b1v));
                }
            }
        }
        #pragma unroll
        for (int mt = 0; mt < 4; mt++)
            #pragma unroll
            for (int nt = 0; nt < 8; nt++) {
                int col = ct*64 + nt*8 + la3*2;
                float bb0 = b2s[col],   w30 = w3s[col];
                float bb1 = b2s[col+1], w31 = w3s[col+1];
                accR[mt*2+0] = fmaf(fmaxf(C[mt][nt][0]+bb0, 0.f), w30,
                               fmaf(fmaxf(C[mt][nt][1]+bb1, 0.f), w31, accR[mt*2+0]));
                accR[mt*2+1] = fmaf(fmaxf(C[mt][nt][2]+bb0, 0.f), w30,
                               fmaf(fmaxf(C[mt][nt][3]+bb1, 0.f), w31, accR[mt*2+1]));
            }
    }
    #pragma unroll
    for (int i = 0; i < 8; i++) {
        accR[i] += __shfl_xor_sync(0xffffffffu, accR[i], 1);
        accR[i] += __shfl_xor_sync(0xffffffffu, accR[i], 2);
    }
    if (la3 == 0) {
        float bz = b3[0];
        size_t base = (size_t)blockIdx.x*512 + r0;
        #pragma unroll
        for (int mt = 0; mt < 4; mt++) {
            g_bias[base + mt*16 + lq]     = accR[2*mt]   + bz;
            g_bias[base + mt*16 + 8 + lq] = accR[2*mt+1] + bz;
        }
    }
}

// ---------------- K6: softmax(4) + attn @ v (writes HALF transposed ao) ----------------
__global__ __launch_bounds__(256) void k6_av() {
    int ng = blockIdx.x; int n = ng >> 3, g = ng & 7;
    int t = threadIdx.x;
    __shared__ float att[64][5];
    __shared__ float vsm[64][5];
    {
        int s = t >> 2, j = t & 3;
        float e = g_sim[(size_t)ng*256 + t] + g_bias[(size_t)ng*256 + t];
        float m = e;
        m = fmaxf(m, __shfl_xor_sync(0xffffffffu, m, 1));
        m = fmaxf(m, __shfl_xor_sync(0xffffffffu, m, 2));
        float ex = __expf(e - m);
        float ssum = ex;
        ssum += __shfl_xor_sync(0xffffffffu, ssum, 1);
        ssum += __shfl_xor_sync(0xffffffffu, ssum, 2);
        att[s][j] = ex / ssum;
        vsm[s][j] = g_v[(size_t)ng*256 + t];
    }
    __syncthreads();
    int tsg = t >> 4, tdg = t & 15;
    __half* ab = g_aoh + (size_t)n*SP*512 + g*64;
    #pragma unroll
    for (int ss=0; ss<4; ss++) {
        int s = tsg*4 + ss;
        float av[4];
        #pragma unroll
        for (int dd=0; dd<4; dd++) {
            int d = tdg*4 + dd;
            av[dd] = att[s][0]*vsm[d][0] + att[s][1]*vsm[d][1]
                   + att[s][2]*vsm[d][2] + att[s][3]*vsm[d][3];
        }
        uint2 p;
        p.x = pack2(av[0], av[1]);
        p.y = pack2(av[2], av[3]);
        *(uint2*)(ab + (size_t)s*512 + tdg*4) = p;
    }
}

// ---------------- K7: final projection; half operands + cp.async double buffer ----------------
__global__ __launch_bounds__(256,2) void k7_out(const float* __restrict__ ob,
                                                float* __restrict__ out) {
    __shared__ __half a_h[2][128*40];
    __shared__ __half w_h[2][128*40];
    int bid = blockIdx.x;
    int m0 = (bid >> 3) * 128, n0 = (bid & 7) * 128;
    int t = threadIdx.x;
    int lane = t & 31, w = t >> 5;
    int lq = lane >> 2, la3 = lane & 3;
    int wm = (w >> 1) * 32, wn = (w & 1) * 64;

    uint32_t abase[2] = { smem_u32(a_h[0]), smem_u32(a_h[1]) };
    uint32_t wbase[2] = { smem_u32(w_h[0]), smem_u32(w_h[1]) };
    int lrow = t >> 2, lc4 = (t & 3) * 16;   // each thread: 1 row, one 16B chunk per half-tile pass

    // per-thread load job: rows lrow and lrow+64 (2 chunks each of the 4 per row? No:
    // 128 rows x 4 chunks = 512 chunks per tile; 256 threads -> 2 chunks each.
    // thread covers (row = t>>1, chunk = (t&1)*2 + i) i in {0,1}
    auto issue_loads = [&](int kc, int b) {
        int row = t >> 1;
        int cbase = (t & 1) * 2;
        #pragma unroll
        for (int i = 0; i < 2; i++) {
            int c4 = cbase + i;                      // 0..3, 8 halves each
            uint32_t da = abase[b] + row*80 + c4*16;
            const __half* sa = g_aoh + (size_t)(m0+row)*512 + kc*32 + c4*8;
            CP16(da, sa);
            uint32_t dw = wbase[b] + row*80 + c4*16;
            const __half* sw = g_owh + (size_t)(n0+row)*512 + kc*32 + c4*8;
            CP16(dw, sw);
        }
        asm volatile("cp.async.commit_group;");
    };

    float C[2][8][4];
    #pragma unroll
    for (int mt=0;mt<2;mt++)
        #pragma unroll
        for (int nt=0;nt<8;nt++)
            #pragma unroll
            for (int i=0;i<4;i++) C[mt][nt][i]=0.f;

    issue_loads(0, 0);
    for (int kc = 0; kc < 16; kc++) {
        int b = kc & 1;
        if (kc < 15) {
            issue_loads(kc+1, b^1);
            asm volatile("cp.async.wait_group 1;");
        } else {
            asm volatile("cp.async.wait_group 0;");
        }
        __syncthreads();
        #pragma unroll
        for (int ks = 0; ks < 2; ks++) {
            int k0 = ks*16 + 2*la3;
            uint32_t a[2][4];
            #pragma unroll
            for (int mt = 0; mt < 2; mt++) {
                int ar = wm + mt*16 + lq;
                a[mt][0] = *(uint32_t*)&a_h[b][ar*40 + k0];
                a[mt][1] = *(uint32_t*)&a_h[b][(ar+8)*40 + k0];
                a[mt][2] = *(uint32_t*)&a_h[b][ar*40 + k0 + 8];
                a[mt][3] = *(uint32_t*)&a_h[b][(ar+8)*40 + k0 + 8];
            }
            #pragma unroll
            for (int nt = 0; nt < 8; nt++) {
                int br = wn + nt*8 + lq;
                uint32_t b0 = *(uint32_t*)&w_h[b][br*40 + k0];
                uint32_t b1v= *(uint32_t*)&w_h[b][br*40 + k0 + 8];
                #pragma unroll
                for (int mt = 0; mt < 2; mt++) {
                    asm volatile(
                        "mma.sync.aligned.m16n8k16.row.col.f32.f16.f16.f32 "
                        "{%0,%1,%2,%3}, {%4,%5,%6,%7}, {%8,%9}, {%0,%1,%2,%3};"
                        : "+f"(C[mt][nt][0]), "+f"(C[mt][nt][1]),
                          "+f"(C[mt][nt][2]), "+f"(C[mt][nt][3])
                        : "r"(a[mt][0]), "r"(a[mt][1]), "r"(a[mt][2]), "r"(a[mt][3]),
                          "r"(b0), "r"(b1v));
                }
            }
        }
        __syncthreads();
    }

    // ---- coalesced epilogue: transpose 128x16 o-groups through smem ----
    float* buf = (float*)a_h;   // 16*132*4 = 8448 B
    int wn_group = (w & 1) * 4;
    for (int og = 0; og < 8; og++) {
        __syncthreads();
        if ((og >> 2) == (w & 1)) {
            int ntb = (og - wn_group) * 2;
            #pragma unroll
            for (int nn = 0; nn < 2; nn++) {
                int nt = ntb + nn;
                int ol = nn*8 + 2*la3;
                #pragma unroll
                for (int mt = 0; mt < 2; mt++) {
                    int ml = wm + mt*16 + lq;
                    buf[ol*132 + ml]       = C[mt][nt][0];
                    buf[(ol+1)*132 + ml]   = C[mt][nt][1];
                    buf[ol*132 + ml + 8]   = C[mt][nt][2];
                    buf[(ol+1)*132 + ml+8] = C[mt][nt][3];
                }
            }
        }
        __syncthreads();
        {
            int o_l = t >> 4, mr = (t & 15) * 8;
            int o = n0 + og*16 + o_l;
            float obv = ob[o];
            int m = m0 + mr;
            int np = m >> 6, s = m & 63;
            int bi = np & 63, q = np >> 6;
            int Y = (q >> 1)*8 + (s >> 3);
            int X = (q & 1)*8;
            float* dst = out + (size_t)bi*262144 + o*256 + Y*16 + X;
            const float* src = buf + o_l*132 + mr;
            float4 v0, v1;
            v0.x = src[0]+obv; v0.y = src[1]+obv; v0.z = src[2]+obv; v0.w = src[3]+obv;
            v1.x = src[4]+obv; v1.y = src[5]+obv; v1.z = src[6]+obv; v1.w = src[7]+obv;
            *(float4*)dst = v0;
            *(float4*)(dst+4) = v1;
        }
    }
}

// ---------------- launch ----------------
extern "C" void kernel_launch(void* const* d_in, const int* in_sizes, int n_in,
                              void* d_out, int out_size) {
    const float* x      = (const float*)d_in[0];
    const float* ln_g   = (const float*)d_in[1];
    const float* ln_b   = (const float*)d_in[2];
    const float* wq     = (const float*)d_in[3];
    const float* wk     = (const float*)d_in[4];
    const float* wv     = (const float*)d_in[5];
    const float* off_w1 = (const float*)d_in[6];
    const float* off_b1 = (const float*)d_in[7];
    const float* off_w2 = (const float*)d_in[8];
    const float* cpb_w1 = (const float*)d_in[9];
    const float* cpb_b1 = (const float*)d_in[10];
    const float* cpb_w2 = (const float*)d_in[11];
    const float* cpb_b2 = (const float*)d_in[12];
    const float* cpb_w3 = (const float*)d_in[13];
    const float* cpb_b3 = (const float*)d_in[14];
    const float* out_w  = (const float*)d_in[15];
    const float* out_b  = (const float*)d_in[16];
    float* out = (float*)d_out;

    static int attr_done = 0;
    if (!attr_done) {
        cudaFuncSetAttribute(k234, cudaFuncAttributeMaxDynamicSharedMemorySize, K234_SMEM);
        attr_done = 1;
    }

    k0w       <<<512, 256>>>(out_w);
    k1_ln     <<<1024, 256>>>(x, ln_g, ln_b);
    k234      <<<2048, 256, K234_SMEM>>>(wq, off_w1, off_b1, off_w2, wk, wv);
    k5_cpb_mma<<<1024, 256>>>(cpb_w1, cpb_b1, cpb_w2, cpb_b2, cpb_w3, cpb_b3);
    k6_av     <<<2048, 256>>>();
    k7_out    <<<1024, 256>>>(out_b, out);
}